// round 1
// baseline (speedup 1.0000x reference)
#include <cuda_runtime.h>
#include <math.h>

// Problem constants
#define Bn 16
#define Nn 2048
#define Dd 512
#define Mm 512
#define DT_C 0.01f

// Scratch (device globals; no runtime allocation allowed)
__device__ float g_K[(size_t)Bn * Mm * Nn];     // 64 MB  RBF kernel matrix
__device__ float g_field[(size_t)Bn * Mm * Dd]; // 16 MB
__device__ float g_tmp[(size_t)Bn * Mm * Dd];   // 16 MB
__device__ float g_tmp2[(size_t)Bn * Mm * Dd];  // 16 MB
__device__ float g_enh[(size_t)Bn * Nn * Dd];   // 64 MB

// ---------------------------------------------------------------------------
// 1) RBF kernel matrix: K[b,m,n] = exp(-(grid[m]-pos[b,n])^2 / (2 sigma^2))
// ---------------------------------------------------------------------------
__global__ void k_rbf(const float* __restrict__ pos,
                      const float* __restrict__ sigma,
                      float* __restrict__ K)
{
    size_t idx = (size_t)blockIdx.x * blockDim.x + threadIdx.x; // < B*M*N
    int n = (int)(idx & (Nn - 1));
    size_t t = idx >> 11;            // / N
    int m = (int)(t & (Mm - 1));
    int b = (int)(t >> 9);           // / M
    float s = __ldg(sigma);
    float inv = 1.0f / (2.0f * s * s);
    float gm = (float)m * (1.0f / (float)(Mm - 1));
    float d = gm - __ldg(&pos[(size_t)b * Nn + n]);
    K[idx] = expf(-d * d * inv);
}

// ---------------------------------------------------------------------------
// Generic SGEMM: C[row, 0..511] = epi(A[row,:Kdim] @ W[:Kdim, 512] + bias) + res
// 64x64 tile, BK=16, 256 threads, 4x4 per thread. All dims exactly divisible.
// Optional batch via blockIdx.z with element strides.
// ---------------------------------------------------------------------------
template <bool GELU>
__global__ __launch_bounds__(256)
void k_gemm(const float* __restrict__ A, const float* __restrict__ W,
            const float* __restrict__ bias, const float* __restrict__ res,
            float* __restrict__ C, int Kdim,
            size_t aStride, size_t bStride, size_t cStride)
{
    __shared__ __align__(16) float As[16][68]; // padded: conflict-lite transpose store, 16B-aligned rows
    __shared__ __align__(16) float Bs[16][64];

    const int tid = threadIdx.x;
    const int tx = tid & 15, ty = tid >> 4;

    const size_t aBase = (size_t)blockIdx.z * aStride + (size_t)(blockIdx.x * 64) * Kdim;
    const float* Wz = W + (size_t)blockIdx.z * bStride;
    const int n0 = blockIdx.y * 64;

    // loader mapping
    const int lr = tid >> 2;         // A tile row 0..63
    const int lk = (tid & 3) * 4;    // A tile k   0,4,8,12
    const int wk = tid >> 4;         // B tile k   0..15
    const int wn = (tid & 15) * 4;   // B tile col 0..60

    float acc[4][4] = {};

    for (int kt = 0; kt < Kdim; kt += 16) {
        float4 av = *reinterpret_cast<const float4*>(&A[aBase + (size_t)lr * Kdim + kt + lk]);
        float4 bv = *reinterpret_cast<const float4*>(&Wz[(size_t)(kt + wk) * 512 + n0 + wn]);
        As[lk + 0][lr] = av.x;
        As[lk + 1][lr] = av.y;
        As[lk + 2][lr] = av.z;
        As[lk + 3][lr] = av.w;
        *reinterpret_cast<float4*>(&Bs[wk][wn]) = bv;
        __syncthreads();

#pragma unroll
        for (int k = 0; k < 16; k++) {
            float4 a = *reinterpret_cast<const float4*>(&As[k][ty * 4]);
            float4 b = *reinterpret_cast<const float4*>(&Bs[k][tx * 4]);
            float ar[4] = {a.x, a.y, a.z, a.w};
            float br[4] = {b.x, b.y, b.z, b.w};
#pragma unroll
            for (int i = 0; i < 4; i++)
#pragma unroll
                for (int j = 0; j < 4; j++)
                    acc[i][j] = fmaf(ar[i], br[j], acc[i][j]);
        }
        __syncthreads();
    }

    const size_t cBase = (size_t)blockIdx.z * cStride;
    const int row0 = blockIdx.x * 64 + ty * 4;
    const int col0 = n0 + tx * 4;
    float bb[4];
#pragma unroll
    for (int j = 0; j < 4; j++) bb[j] = bias ? __ldg(&bias[col0 + j]) : 0.0f;

#pragma unroll
    for (int i = 0; i < 4; i++) {
        size_t o = cBase + (size_t)(row0 + i) * 512 + col0;
#pragma unroll
        for (int j = 0; j < 4; j++) {
            float v = acc[i][j] + bb[j];
            if (GELU) {
                // jax.nn.gelu default (tanh approximation)
                float x3 = v * v * v;
                v = 0.5f * v * (1.0f + tanhf(0.7978845608028654f * (v + 0.044715f * x3)));
            }
            if (res) v += res[o + j];
            C[o + j] = v;
        }
    }
}

// ---------------------------------------------------------------------------
// 2) Head mixing: mix[b,m,h*64+d] = sum_k alpha[h,k] * field[b,m,k*64+d]
// ---------------------------------------------------------------------------
__global__ void k_headmix(const float* __restrict__ alpha,
                          const float* __restrict__ field,
                          float* __restrict__ mix)
{
    size_t idx = (size_t)blockIdx.x * 256 + threadIdx.x; // < B*M*D
    int dcol = (int)(idx & 511);
    int h = dcol >> 6;
    int dd = dcol & 63;
    size_t base = idx - dcol;
    float s = 0.0f;
#pragma unroll
    for (int k = 0; k < 8; k++)
        s = fmaf(__ldg(&alpha[h * 8 + k]), field[base + k * 64 + dd], s);
    mix[idx] = s;
}

// ---------------------------------------------------------------------------
// 3) One explicit-Euler diffusion step along M (Neumann/edge-padded Laplacian)
// ---------------------------------------------------------------------------
__global__ void k_diffuse(const float* __restrict__ in, float* __restrict__ out,
                          const float* __restrict__ coef)
{
    size_t idx = (size_t)blockIdx.x * 256 + threadIdx.x; // < B*M*D
    int d = (int)(idx & 511);
    int m = (int)((idx >> 9) & 511);
    float c = in[idx];
    float l = (m > 0) ? in[idx - 512] : c;
    float r = (m < Mm - 1) ? in[idx + 512] : c;
    out[idx] = fmaf(DT_C * __ldg(&coef[d]), l + r - 2.0f * c, c);
}

// ---------------------------------------------------------------------------
// 4) Linear sampling at token positions + residual + LayerNorm -> enh
//    one block (128 threads) per token row; D=512 -> 4 elems/thread
// ---------------------------------------------------------------------------
__global__ __launch_bounds__(128)
void k_sample_ln(const float* __restrict__ pos, const float* __restrict__ emb,
                 const float* __restrict__ field,
                 const float* __restrict__ gam, const float* __restrict__ bet,
                 float* __restrict__ enh)
{
    __shared__ float ssum[4], ssq[4], sstat[2];
    int row = blockIdx.x;         // b*N + n
    int b = row >> 11;
    float p = __ldg(&pos[row]);
    float u = fminf(fmaxf(p, 0.0f), 1.0f) * (float)(Mm - 1);
    int i0 = (int)u;              // floor (u >= 0)
    if (i0 > Mm - 2) i0 = Mm - 2;
    float w = u - (float)i0;

    const float* f0 = field + ((size_t)b * Mm + i0) * Dd;
    const float* e = emb + (size_t)row * Dd;

    int t = threadIdx.x;
    float x[4];
    float sum = 0.0f, sq = 0.0f;
#pragma unroll
    for (int j = 0; j < 4; j++) {
        int d = t + j * 128;
        float a = f0[d];
        float v = fmaf(w, f0[d + Dd] - a, a) + e[d];
        x[j] = v;
        sum += v;
        sq = fmaf(v, v, sq);
    }
#pragma unroll
    for (int o = 16; o > 0; o >>= 1) {
        sum += __shfl_down_sync(0xffffffffu, sum, o);
        sq += __shfl_down_sync(0xffffffffu, sq, o);
    }
    int wid = t >> 5, lane = t & 31;
    if (lane == 0) { ssum[wid] = sum; ssq[wid] = sq; }
    __syncthreads();
    if (t == 0) {
        float S = ssum[0] + ssum[1] + ssum[2] + ssum[3];
        float Q = ssq[0] + ssq[1] + ssq[2] + ssq[3];
        float mu = S * (1.0f / Dd);
        float var = Q * (1.0f / Dd) - mu * mu;
        sstat[0] = mu;
        sstat[1] = rsqrtf(var + 1e-5f);
    }
    __syncthreads();
    float mu = sstat[0], inv = sstat[1];
    size_t o = (size_t)row * Dd;
#pragma unroll
    for (int j = 0; j < 4; j++) {
        int d = t + j * 128;
        enh[o + d] = (x[j] - mu) * inv * __ldg(&gam[d]) + __ldg(&bet[d]);
    }
}

// ---------------------------------------------------------------------------
// 5) Final residual + LayerNorm (in-place on out): out = LN(out + enh)
// ---------------------------------------------------------------------------
__global__ __launch_bounds__(128)
void k_ln2(const float* __restrict__ enh,
           const float* __restrict__ gam, const float* __restrict__ bet,
           float* __restrict__ out)
{
    __shared__ float ssum[4], ssq[4], sstat[2];
    int row = blockIdx.x;
    size_t o = (size_t)row * Dd;
    int t = threadIdx.x;
    float x[4];
    float sum = 0.0f, sq = 0.0f;
#pragma unroll
    for (int j = 0; j < 4; j++) {
        int d = t + j * 128;
        float v = out[o + d] + enh[o + d];
        x[j] = v;
        sum += v;
        sq = fmaf(v, v, sq);
    }
#pragma unroll
    for (int s = 16; s > 0; s >>= 1) {
        sum += __shfl_down_sync(0xffffffffu, sum, s);
        sq += __shfl_down_sync(0xffffffffu, sq, s);
    }
    int wid = t >> 5, lane = t & 31;
    if (lane == 0) { ssum[wid] = sum; ssq[wid] = sq; }
    __syncthreads();
    if (t == 0) {
        float S = ssum[0] + ssum[1] + ssum[2] + ssum[3];
        float Q = ssq[0] + ssq[1] + ssq[2] + ssq[3];
        float mu = S * (1.0f / Dd);
        float var = Q * (1.0f / Dd) - mu * mu;
        sstat[0] = mu;
        sstat[1] = rsqrtf(var + 1e-5f);
    }
    __syncthreads();
    float mu = sstat[0], inv = sstat[1];
#pragma unroll
    for (int j = 0; j < 4; j++) {
        int d = t + j * 128;
        out[o + d] = (x[j] - mu) * inv * __ldg(&gam[d]) + __ldg(&bet[d]);
    }
}

// ---------------------------------------------------------------------------
extern "C" void kernel_launch(void* const* d_in, const int* in_sizes, int n_in,
                              void* d_out, int out_size)
{
    const float* emb   = (const float*)d_in[0];
    const float* pos   = (const float*)d_in[1];
    const float* sigma = (const float*)d_in[2];
    const float* alpha = (const float*)d_in[3];
    const float* w_int = (const float*)d_in[4];
    const float* b_int = (const float*)d_in[5];
    const float* dcoef = (const float*)d_in[6];
    const float* W1    = (const float*)d_in[7];
    const float* b1    = (const float*)d_in[8];
    const float* W2    = (const float*)d_in[9];
    const float* b2    = (const float*)d_in[10];
    const float* ecoef = (const float*)d_in[11];
    const float* ln1g  = (const float*)d_in[12];
    const float* ln1b  = (const float*)d_in[13];
    const float* Wout  = (const float*)d_in[14];
    const float* bout  = (const float*)d_in[15];
    const float* ln2g  = (const float*)d_in[16];
    const float* ln2b  = (const float*)d_in[17];
    float* out = (float*)d_out;

    float *K, *field, *tmp, *tmp2, *enh;
    cudaGetSymbolAddress((void**)&K, g_K);
    cudaGetSymbolAddress((void**)&field, g_field);
    cudaGetSymbolAddress((void**)&tmp, g_tmp);
    cudaGetSymbolAddress((void**)&tmp2, g_tmp2);
    cudaGetSymbolAddress((void**)&enh, g_enh);

    const int nbBMD = (Bn * Mm * Dd) / 256;

    // 1) RBF kernel matrix
    k_rbf<<<(int)(((size_t)Bn * Mm * Nn) / 256), 256>>>(pos, sigma, K);

    // 2) field = K @ emb  (batched over B; Kdim = N = 2048)
    dim3 g1(Mm / 64, Dd / 64, Bn);
    k_gemm<false><<<g1, 256>>>(K, emb, nullptr, nullptr, field, Nn,
                               (size_t)Mm * Nn, (size_t)Nn * Dd, (size_t)Mm * Dd);

    // 3) head mixing: tmp = mix
    k_headmix<<<nbBMD, 256>>>(alpha, field, tmp);

    // 4) tmp2 = field + tmp @ w_int + b_int
    dim3 g2((Bn * Mm) / 64, Dd / 64, 1);
    k_gemm<false><<<g2, 256>>>(tmp, w_int, b_int, field, tmp2, Dd, 0, 0, 0);

    // 5) diffusion x3 (diff_coef): tmp2 -> field -> tmp2 -> field
    k_diffuse<<<nbBMD, 256>>>(tmp2, field, dcoef);
    k_diffuse<<<nbBMD, 256>>>(field, tmp2, dcoef);
    k_diffuse<<<nbBMD, 256>>>(tmp2, field, dcoef);

    // 6) tmp = gelu(field @ W1 + b1)
    k_gemm<true><<<g2, 256>>>(field, W1, b1, nullptr, tmp, Dd, 0, 0, 0);

    // 7) tmp2 = field + tmp @ W2 + b2
    k_gemm<false><<<g2, 256>>>(tmp, W2, b2, field, tmp2, Dd, 0, 0, 0);

    // 8) diffusion x3 (evo_coef): tmp2 -> field -> tmp2 -> field
    k_diffuse<<<nbBMD, 256>>>(tmp2, field, ecoef);
    k_diffuse<<<nbBMD, 256>>>(field, tmp2, ecoef);
    k_diffuse<<<nbBMD, 256>>>(tmp2, field, ecoef);

    // 9) enh = LN1(sample(field) + emb)
    k_sample_ln<<<Bn * Nn, 128>>>(pos, emb, field, ln1g, ln1b, enh);

    // 10) out = enh @ Wout + bout
    dim3 g7((Bn * Nn) / 64, Dd / 64, 1);
    k_gemm<false><<<g7, 256>>>(enh, Wout, bout, nullptr, out, Dd, 0, 0, 0);

    // 11) out = LN2(out + enh)
    k_ln2<<<Bn * Nn, 128>>>(enh, ln2g, ln2b, out);
}

// round 2
// speedup vs baseline: 1.1714x; 1.1714x over previous
#include <cuda_runtime.h>
#include <math.h>

// Problem constants
#define Bn 16
#define Nn 2048
#define Dd 512
#define Mm 512
#define DT_C 0.01f

// Scratch (device globals; no runtime allocation allowed)
__device__ float g_field[(size_t)Bn * Mm * Dd]; // 16 MB
__device__ float g_tmp[(size_t)Bn * Mm * Dd];   // 16 MB
__device__ float g_tmp2[(size_t)Bn * Mm * Dd];  // 16 MB
__device__ float g_enh[(size_t)Bn * Nn * Dd];   // 64 MB

// ---------------------------------------------------------------------------
// SGEMM 128x128x16, 256 threads, 8x8 per thread, register-prefetch pipeline.
// C[row, n] = epi(A[row, :Kdim] @ W[:Kdim, 512] + bias) (+ res)
// RBF mode: A element (m, k) generated as exp(-(grid[m]-pos[k])^2/(2 sigma^2))
// Batched over blockIdx.z with element strides.
// ---------------------------------------------------------------------------
template <bool RBF, bool GELU>
__global__ __launch_bounds__(256)
void k_gemm128(const float* __restrict__ A, const float* __restrict__ W,
               const float* __restrict__ bias, const float* __restrict__ res,
               float* __restrict__ C, int Kdim,
               size_t aStride, size_t bStride, size_t cStride,
               const float* __restrict__ sigma)
{
    __shared__ __align__(16) float As[16][132];
    __shared__ __align__(16) float Bs[16][128];

    const int t = threadIdx.x;
    const int tx = t & 15, ty = t >> 4;

    // loader mapping
    const int rowL = t >> 1;          // A row 0..127 (2 threads per row)
    const int kc   = (t & 1) * 8;     // A k offset 0 or 8
    const int kB   = t >> 4;          // B k 0..15
    const int cB   = (t & 15) * 8;    // B col 0..120

    const float* Az = A + (size_t)blockIdx.z * aStride;
    const float* Wz = W + (size_t)blockIdx.z * bStride;
    const int m0 = blockIdx.x * 128;
    const int n0 = blockIdx.y * 128;

    float inv = 0.0f, gm = 0.0f;
    if (RBF) {
        float s = __ldg(sigma);
        inv = 1.0f / (2.0f * s * s);
        gm = (float)(m0 + rowL) * (1.0f / 511.0f);
    }

    float aR[8], bR[8];

    // prefetch tile kt = 0
    {
        if (RBF) {
            float4 p0 = *(const float4*)&Az[kc];
            float4 p1 = *(const float4*)&Az[kc + 4];
            float pv[8] = {p0.x, p0.y, p0.z, p0.w, p1.x, p1.y, p1.z, p1.w};
#pragma unroll
            for (int i = 0; i < 8; i++) {
                float d = gm - pv[i];
                aR[i] = expf(-d * d * inv);
            }
        } else {
            const float* ap = &Az[(size_t)(m0 + rowL) * Kdim + kc];
            float4 a0 = *(const float4*)ap;
            float4 a1 = *(const float4*)(ap + 4);
            aR[0] = a0.x; aR[1] = a0.y; aR[2] = a0.z; aR[3] = a0.w;
            aR[4] = a1.x; aR[5] = a1.y; aR[6] = a1.z; aR[7] = a1.w;
        }
        const float* bp = &Wz[(size_t)kB * 512 + n0 + cB];
        float4 b0 = *(const float4*)bp;
        float4 b1 = *(const float4*)(bp + 4);
        bR[0] = b0.x; bR[1] = b0.y; bR[2] = b0.z; bR[3] = b0.w;
        bR[4] = b1.x; bR[5] = b1.y; bR[6] = b1.z; bR[7] = b1.w;
    }

    float acc[8][8] = {};

    for (int kt = 0; kt < Kdim; kt += 16) {
        __syncthreads();
#pragma unroll
        for (int i = 0; i < 8; i++) As[kc + i][rowL] = aR[i];
        *(float4*)&Bs[kB][cB]     = make_float4(bR[0], bR[1], bR[2], bR[3]);
        *(float4*)&Bs[kB][cB + 4] = make_float4(bR[4], bR[5], bR[6], bR[7]);
        __syncthreads();

        const int kt2 = kt + 16;
        if (kt2 < Kdim) {
            if (RBF) {
                float4 p0 = *(const float4*)&Az[kt2 + kc];
                float4 p1 = *(const float4*)&Az[kt2 + kc + 4];
                float pv[8] = {p0.x, p0.y, p0.z, p0.w, p1.x, p1.y, p1.z, p1.w};
#pragma unroll
                for (int i = 0; i < 8; i++) {
                    float d = gm - pv[i];
                    aR[i] = expf(-d * d * inv);
                }
            } else {
                const float* ap = &Az[(size_t)(m0 + rowL) * Kdim + kt2 + kc];
                float4 a0 = *(const float4*)ap;
                float4 a1 = *(const float4*)(ap + 4);
                aR[0] = a0.x; aR[1] = a0.y; aR[2] = a0.z; aR[3] = a0.w;
                aR[4] = a1.x; aR[5] = a1.y; aR[6] = a1.z; aR[7] = a1.w;
            }
            const float* bp = &Wz[(size_t)(kt2 + kB) * 512 + n0 + cB];
            float4 b0 = *(const float4*)bp;
            float4 b1 = *(const float4*)(bp + 4);
            bR[0] = b0.x; bR[1] = b0.y; bR[2] = b0.z; bR[3] = b0.w;
            bR[4] = b1.x; bR[5] = b1.y; bR[6] = b1.z; bR[7] = b1.w;
        }

#pragma unroll
        for (int k = 0; k < 16; k++) {
            float4 a0 = *(const float4*)&As[k][ty * 8];
            float4 a1 = *(const float4*)&As[k][ty * 8 + 4];
            float4 b0 = *(const float4*)&Bs[k][tx * 8];
            float4 b1 = *(const float4*)&Bs[k][tx * 8 + 4];
            float av[8] = {a0.x, a0.y, a0.z, a0.w, a1.x, a1.y, a1.z, a1.w};
            float bv[8] = {b0.x, b0.y, b0.z, b0.w, b1.x, b1.y, b1.z, b1.w};
#pragma unroll
            for (int i = 0; i < 8; i++)
#pragma unroll
                for (int j = 0; j < 8; j++)
                    acc[i][j] = fmaf(av[i], bv[j], acc[i][j]);
        }
    }

    // epilogue
    const size_t cBase = (size_t)blockIdx.z * cStride;
    float bb[8];
#pragma unroll
    for (int j = 0; j < 8; j++)
        bb[j] = bias ? __ldg(&bias[n0 + tx * 8 + j]) : 0.0f;

#pragma unroll
    for (int i = 0; i < 8; i++) {
        size_t o = cBase + (size_t)(m0 + ty * 8 + i) * 512 + n0 + tx * 8;
        float v[8];
#pragma unroll
        for (int j = 0; j < 8; j++) {
            float x = acc[i][j] + bb[j];
            if (GELU) {
                float x3 = x * x * x;
                x = 0.5f * x * (1.0f + tanhf(0.7978845608028654f * (x + 0.044715f * x3)));
            }
            v[j] = x;
        }
        if (res) {
            float4 r0 = *(const float4*)&res[o];
            float4 r1 = *(const float4*)&res[o + 4];
            v[0] += r0.x; v[1] += r0.y; v[2] += r0.z; v[3] += r0.w;
            v[4] += r1.x; v[5] += r1.y; v[6] += r1.z; v[7] += r1.w;
        }
        *(float4*)&C[o]     = make_float4(v[0], v[1], v[2], v[3]);
        *(float4*)&C[o + 4] = make_float4(v[4], v[5], v[6], v[7]);
    }
}

// ---------------------------------------------------------------------------
// Head mixing: mix[b,m,h*64+d] = sum_k alpha[h,k] * field[b,m,k*64+d]
// ---------------------------------------------------------------------------
__global__ void k_headmix(const float* __restrict__ alpha,
                          const float* __restrict__ field,
                          float* __restrict__ mix)
{
    size_t idx = (size_t)blockIdx.x * 256 + threadIdx.x; // < B*M*D
    int dcol = (int)(idx & 511);
    int h = dcol >> 6;
    int dd = dcol & 63;
    size_t base = idx - dcol;
    float s = 0.0f;
#pragma unroll
    for (int k = 0; k < 8; k++)
        s = fmaf(__ldg(&alpha[h * 8 + k]), field[base + k * 64 + dd], s);
    mix[idx] = s;
}

// ---------------------------------------------------------------------------
// 3 fused explicit-Euler diffusion steps along M, resident in shared memory.
// One block = one (batch, 8 consecutive d-columns) strip over all 512 m.
// ---------------------------------------------------------------------------
__global__ __launch_bounds__(256)
void k_diffuse3(const float* __restrict__ in, float* __restrict__ out,
                const float* __restrict__ coef)
{
    __shared__ float s[512 * 8]; // s[m*8 + d]
    const int t = threadIdx.x;
    const int b = blockIdx.x >> 6;
    const int d0 = (blockIdx.x & 63) * 8;
    const int dl = t & 7;

    const size_t gbase = ((size_t)b * Mm) * Dd + d0;
    const float c = DT_C * __ldg(&coef[d0 + dl]);

    // load strip: thread handles idx = t + i*256 (m = idx>>3, d = idx&7)
#pragma unroll
    for (int i = 0; i < 16; i++) {
        int idx = t + i * 256;
        int m = idx >> 3;
        s[idx] = in[gbase + (size_t)m * Dd + dl];
    }
    __syncthreads();

#pragma unroll
    for (int step = 0; step < 3; step++) {
        float nv[16];
#pragma unroll
        for (int i = 0; i < 16; i++) {
            int idx = t + i * 256;
            int m = idx >> 3;
            float v = s[idx];
            float l = (m > 0)   ? s[idx - 8] : v;
            float r = (m < 511) ? s[idx + 8] : v;
            nv[i] = fmaf(c, l + r - 2.0f * v, v);
        }
        __syncthreads();
#pragma unroll
        for (int i = 0; i < 16; i++) s[t + i * 256] = nv[i];
        __syncthreads();
    }

#pragma unroll
    for (int i = 0; i < 16; i++) {
        int idx = t + i * 256;
        int m = idx >> 3;
        out[gbase + (size_t)m * Dd + dl] = s[idx];
    }
}

// ---------------------------------------------------------------------------
// Linear sampling at token positions + residual + LayerNorm -> enh
// ---------------------------------------------------------------------------
__global__ __launch_bounds__(128)
void k_sample_ln(const float* __restrict__ pos, const float* __restrict__ emb,
                 const float* __restrict__ field,
                 const float* __restrict__ gam, const float* __restrict__ bet,
                 float* __restrict__ enh)
{
    __shared__ float ssum[4], ssq[4], sstat[2];
    int row = blockIdx.x;         // b*N + n
    int b = row >> 11;
    float p = __ldg(&pos[row]);
    float u = fminf(fmaxf(p, 0.0f), 1.0f) * (float)(Mm - 1);
    int i0 = (int)u;
    if (i0 > Mm - 2) i0 = Mm - 2;
    float w = u - (float)i0;

    const float* f0 = field + ((size_t)b * Mm + i0) * Dd;
    const float* e = emb + (size_t)row * Dd;

    int t = threadIdx.x;
    float x[4];
    float sum = 0.0f, sq = 0.0f;
#pragma unroll
    for (int j = 0; j < 4; j++) {
        int d = t + j * 128;
        float a = f0[d];
        float v = fmaf(w, f0[d + Dd] - a, a) + e[d];
        x[j] = v;
        sum += v;
        sq = fmaf(v, v, sq);
    }
#pragma unroll
    for (int o = 16; o > 0; o >>= 1) {
        sum += __shfl_down_sync(0xffffffffu, sum, o);
        sq += __shfl_down_sync(0xffffffffu, sq, o);
    }
    int wid = t >> 5, lane = t & 31;
    if (lane == 0) { ssum[wid] = sum; ssq[wid] = sq; }
    __syncthreads();
    if (t == 0) {
        float S = ssum[0] + ssum[1] + ssum[2] + ssum[3];
        float Q = ssq[0] + ssq[1] + ssq[2] + ssq[3];
        float mu = S * (1.0f / Dd);
        float var = Q * (1.0f / Dd) - mu * mu;
        sstat[0] = mu;
        sstat[1] = rsqrtf(var + 1e-5f);
    }
    __syncthreads();
    float mu = sstat[0], invs = sstat[1];
    size_t o = (size_t)row * Dd;
#pragma unroll
    for (int j = 0; j < 4; j++) {
        int d = t + j * 128;
        enh[o + d] = (x[j] - mu) * invs * __ldg(&gam[d]) + __ldg(&bet[d]);
    }
}

// ---------------------------------------------------------------------------
// Final residual + LayerNorm (in-place on out): out = LN(out + enh)
// ---------------------------------------------------------------------------
__global__ __launch_bounds__(128)
void k_ln2(const float* __restrict__ enh,
           const float* __restrict__ gam, const float* __restrict__ bet,
           float* __restrict__ out)
{
    __shared__ float ssum[4], ssq[4], sstat[2];
    int row = blockIdx.x;
    size_t o = (size_t)row * Dd;
    int t = threadIdx.x;
    float x[4];
    float sum = 0.0f, sq = 0.0f;
#pragma unroll
    for (int j = 0; j < 4; j++) {
        int d = t + j * 128;
        float v = out[o + d] + enh[o + d];
        x[j] = v;
        sum += v;
        sq = fmaf(v, v, sq);
    }
#pragma unroll
    for (int s = 16; s > 0; s >>= 1) {
        sum += __shfl_down_sync(0xffffffffu, sum, s);
        sq += __shfl_down_sync(0xffffffffu, sq, s);
    }
    int wid = t >> 5, lane = t & 31;
    if (lane == 0) { ssum[wid] = sum; ssq[wid] = sq; }
    __syncthreads();
    if (t == 0) {
        float S = ssum[0] + ssum[1] + ssum[2] + ssum[3];
        float Q = ssq[0] + ssq[1] + ssq[2] + ssq[3];
        float mu = S * (1.0f / Dd);
        float var = Q * (1.0f / Dd) - mu * mu;
        sstat[0] = mu;
        sstat[1] = rsqrtf(var + 1e-5f);
    }
    __syncthreads();
    float mu = sstat[0], invs = sstat[1];
#pragma unroll
    for (int j = 0; j < 4; j++) {
        int d = t + j * 128;
        out[o + d] = (x[j] - mu) * invs * __ldg(&gam[d]) + __ldg(&bet[d]);
    }
}

// ---------------------------------------------------------------------------
extern "C" void kernel_launch(void* const* d_in, const int* in_sizes, int n_in,
                              void* d_out, int out_size)
{
    const float* emb   = (const float*)d_in[0];
    const float* pos   = (const float*)d_in[1];
    const float* sigma = (const float*)d_in[2];
    const float* alpha = (const float*)d_in[3];
    const float* w_int = (const float*)d_in[4];
    const float* b_int = (const float*)d_in[5];
    const float* dcoef = (const float*)d_in[6];
    const float* W1    = (const float*)d_in[7];
    const float* b1    = (const float*)d_in[8];
    const float* W2    = (const float*)d_in[9];
    const float* b2    = (const float*)d_in[10];
    const float* ecoef = (const float*)d_in[11];
    const float* ln1g  = (const float*)d_in[12];
    const float* ln1b  = (const float*)d_in[13];
    const float* Wout  = (const float*)d_in[14];
    const float* bout  = (const float*)d_in[15];
    const float* ln2g  = (const float*)d_in[16];
    const float* ln2b  = (const float*)d_in[17];
    float* out = (float*)d_out;

    float *field, *tmp, *tmp2, *enh;
    cudaGetSymbolAddress((void**)&field, g_field);
    cudaGetSymbolAddress((void**)&tmp, g_tmp);
    cudaGetSymbolAddress((void**)&tmp2, g_tmp2);
    cudaGetSymbolAddress((void**)&enh, g_enh);

    const int nbBMD = (Bn * Mm * Dd) / 256;

    // 1) field = RBF(pos) @ emb  (batched over B; Kdim = N = 2048, exp fused)
    dim3 g1(Mm / 128, Dd / 128, Bn);
    k_gemm128<true, false><<<g1, 256>>>(pos, emb, nullptr, nullptr, field, Nn,
                                        (size_t)Nn, (size_t)Nn * Dd,
                                        (size_t)Mm * Dd, sigma);

    // 2) head mixing: tmp = mix
    k_headmix<<<nbBMD, 256>>>(alpha, field, tmp);

    // 3) tmp2 = field + tmp @ w_int + b_int
    dim3 g2((Bn * Mm) / 128, Dd / 128, 1);
    k_gemm128<false, false><<<g2, 256>>>(tmp, w_int, b_int, field, tmp2, Dd,
                                         0, 0, 0, nullptr);

    // 4) diffusion x3 (diff_coef): tmp2 -> field
    k_diffuse3<<<Bn * (Dd / 8), 256>>>(tmp2, field, dcoef);

    // 5) tmp = gelu(field @ W1 + b1)
    k_gemm128<false, true><<<g2, 256>>>(field, W1, b1, nullptr, tmp, Dd,
                                        0, 0, 0, nullptr);

    // 6) tmp2 = field + tmp @ W2 + b2
    k_gemm128<false, false><<<g2, 256>>>(tmp, W2, b2, field, tmp2, Dd,
                                         0, 0, 0, nullptr);

    // 7) diffusion x3 (evo_coef): tmp2 -> field
    k_diffuse3<<<Bn * (Dd / 8), 256>>>(tmp2, field, ecoef);

    // 8) enh = LN1(sample(field) + emb)
    k_sample_ln<<<Bn * Nn, 128>>>(pos, emb, field, ln1g, ln1b, enh);

    // 9) out = enh @ Wout + bout
    dim3 g7((Bn * Nn) / 128, Dd / 128, 1);
    k_gemm128<false, false><<<g7, 256>>>(enh, Wout, bout, nullptr, out, Dd,
                                         0, 0, 0, nullptr);

    // 10) out = LN2(out + enh)
    k_ln2<<<Bn * Nn, 128>>>(enh, ln2g, ln2b, out);
}

// round 4
// speedup vs baseline: 2.6548x; 2.2663x over previous
#include <cuda_runtime.h>
#include <cuda_bf16.h>
#include <math.h>
#include <stdint.h>

#define Bn 16
#define Nn 2048
#define Dd 512
#define Mm 512
#define DT_C 0.01f

typedef __nv_bfloat16 bf16;

// ------------------------- device scratch (no runtime alloc) ---------------
__device__ bf16 g_h1[(size_t)32768 * 512];   // 32MB  (K-RBF hi / field hi / enh hi)
__device__ bf16 g_l1[(size_t)32768 * 512];   // 32MB
__device__ bf16 g_h2[(size_t)8192 * 512];    // 8MB   (gelu hi)
__device__ bf16 g_l2[(size_t)8192 * 512];    // 8MB
__device__ bf16 g_ebh[(size_t)Bn * Dd * Nn]; // 32MB  embT hi  [b, d, t]
__device__ bf16 g_ebl[(size_t)Bn * Dd * Nn]; // 32MB
__device__ bf16 g_wh[4][512 * 512];          // 2MB   weight^T hi [n, k]
__device__ bf16 g_wl[4][512 * 512];
__device__ float g_field[(size_t)Bn * Mm * Dd]; // 16MB
__device__ float g_tmp2[(size_t)Bn * Mm * Dd];  // 16MB
__device__ float g_enh[(size_t)Bn * Nn * Dd];   // 64MB

// ------------------------- helpers -----------------------------------------
__device__ __forceinline__ uint32_t smem_u32(const void* p) {
    uint32_t a;
    asm("{ .reg .u64 t; cvta.to.shared.u64 t, %1; cvt.u32.u64 %0, t; }" : "=r"(a) : "l"(p));
    return a;
}
__device__ __forceinline__ uint32_t pack_bf2(float a, float b) {
    __nv_bfloat162 t = __floats2bfloat162_rn(a, b);
    return *reinterpret_cast<uint32_t*>(&t);
}
__device__ __forceinline__ void cp16(uint32_t dst, const void* src) {
    asm volatile("cp.async.cg.shared.global [%0], [%1], 16;" :: "r"(dst), "l"(src));
}
__device__ __forceinline__ void cp_commit() {
    asm volatile("cp.async.commit_group;");
}
__device__ __forceinline__ void cp_wait1() {
    asm volatile("cp.async.wait_group 1;");
}
__device__ __forceinline__ void ldm_x4(uint32_t* r, uint32_t a) {
    asm volatile("ldmatrix.sync.aligned.m8n8.x4.shared.b16 {%0,%1,%2,%3}, [%4];"
                 : "=r"(r[0]), "=r"(r[1]), "=r"(r[2]), "=r"(r[3]) : "r"(a));
}
__device__ __forceinline__ void ldm_x2(uint32_t* r, uint32_t a) {
    asm volatile("ldmatrix.sync.aligned.m8n8.x2.shared.b16 {%0,%1}, [%2];"
                 : "=r"(r[0]), "=r"(r[1]) : "r"(a));
}
__device__ __forceinline__ void mma_bf16(float* c, const uint32_t* a, const uint32_t* b) {
    asm volatile(
        "mma.sync.aligned.m16n8k16.row.col.f32.bf16.bf16.f32 "
        "{%0,%1,%2,%3}, {%4,%5,%6,%7}, {%8,%9}, {%0,%1,%2,%3};"
        : "+f"(c[0]), "+f"(c[1]), "+f"(c[2]), "+f"(c[3])
        : "r"(a[0]), "r"(a[1]), "r"(a[2]), "r"(a[3]), "r"(b[0]), "r"(b[1]));
}

// ------------------------- HMMA GEMM ----------------------------------------
// D[128,128] CTA tile; A,B hi/lo bf16 K-major ([row][k]); 3-pass hi/lo split.
// SMEM: 2 buffers x (Ah,Al,Bh,Bl) x 16KB = 128KB dynamic.
#define SMEM_SZ (2 * 4 * 16384)

template <bool GELU, bool RES, bool WF32, bool WHILO>
__global__ __launch_bounds__(256)
void k_gemm_mma(const bf16* __restrict__ Ah, const bf16* __restrict__ Al,
                size_t aRS, size_t aBS,
                const bf16* __restrict__ Bh, const bf16* __restrict__ Bl,
                size_t bRS, size_t bBS,
                const float* __restrict__ bias, const float* __restrict__ resp,
                float* __restrict__ C, bf16* __restrict__ Ch, bf16* __restrict__ Cl,
                size_t cBS, int Kdim)
{
    extern __shared__ char smem[];
    const uint32_t sb = smem_u32(smem);
    const int t = threadIdx.x;
    const int wid = t >> 5;
    const int lane = t & 31;
    const int warp_m = wid & 1;   // 2 warps over M (64 rows each)
    const int warp_n = wid >> 1;  // 4 warps over N (32 cols each)

    const int m0 = blockIdx.x * 128;
    const int n0 = blockIdx.y * 128;
    const int z = blockIdx.z;

    const bf16* pAh = Ah + (size_t)z * aBS;
    const bf16* pAl = Al + (size_t)z * aBS;
    const bf16* pBh = Bh + (size_t)z * bBS;
    const bf16* pBl = Bl + (size_t)z * bBS;

    // loader mapping: per chunk, per tile: 4 iters; id = t + i*256
    // row = id>>3 (0..127), 16B-seg = id&7
    const int NC = Kdim >> 6;

    auto load_chunk = [&](int c) {
        const uint32_t buf = sb + (uint32_t)(c & 1) * 65536u;
        const int k0 = c << 6;
#pragma unroll
        for (int i = 0; i < 4; i++) {
            int id = t + i * 256;
            int row = id >> 3;
            int seg = id & 7;
            uint32_t soff = (uint32_t)row * 128 + (uint32_t)((seg * 16) ^ ((row & 7) << 4));
            size_t ae = (size_t)(m0 + row) * aRS + k0 + seg * 8;
            size_t be = (size_t)(n0 + row) * bRS + k0 + seg * 8;
            cp16(buf + soff,          pAh + ae);
            cp16(buf + 16384 + soff,  pAl + ae);
            cp16(buf + 32768 + soff,  pBh + be);
            cp16(buf + 49152 + soff,  pBl + be);
        }
    };

    load_chunk(0); cp_commit();
    load_chunk(1); cp_commit();

    // fragment address precomputation
    const int rowA = warp_m * 64 + (lane & 15);
    const uint32_t maskA = (uint32_t)(rowA & 7) << 4;
    const uint32_t kbA = (uint32_t)(lane >> 4) * 16;
    const int rowB = warp_n * 32 + (lane & 7);
    const uint32_t maskB = (uint32_t)(rowB & 7) << 4;
    const uint32_t kbB = (uint32_t)((lane >> 3) & 1) * 16;

    float acc[4][4][4] = {};

    for (int c = 0; c < NC; c++) {
        cp_wait1();
        __syncthreads();
        const uint32_t buf = sb + (uint32_t)(c & 1) * 65536u;
        const uint32_t aBaseH = buf + (uint32_t)rowA * 128;
        const uint32_t aBaseL = aBaseH + 16384;
        const uint32_t bBaseH = buf + 32768 + (uint32_t)rowB * 128;
        const uint32_t bBaseL = bBaseH + 16384;

#pragma unroll
        for (int k16 = 0; k16 < 4; k16++) {
            const uint32_t koffA = ((uint32_t)k16 * 32 + kbA) ^ maskA;
            const uint32_t koffB = ((uint32_t)k16 * 32 + kbB) ^ maskB;
            uint32_t ah[4][4], al[4][4], bh[4][2], bl[4][2];
#pragma unroll
            for (int mi = 0; mi < 4; mi++) {
                ldm_x4(ah[mi], aBaseH + mi * 2048 + koffA);
                ldm_x4(al[mi], aBaseL + mi * 2048 + koffA);
            }
#pragma unroll
            for (int ni = 0; ni < 4; ni++) {
                ldm_x2(bh[ni], bBaseH + ni * 1024 + koffB);
                ldm_x2(bl[ni], bBaseL + ni * 1024 + koffB);
            }
#pragma unroll
            for (int mi = 0; mi < 4; mi++)
#pragma unroll
                for (int ni = 0; ni < 4; ni++) {
                    mma_bf16(acc[mi][ni], ah[mi], bh[ni]);
                    mma_bf16(acc[mi][ni], ah[mi], bl[ni]);
                    mma_bf16(acc[mi][ni], al[mi], bh[ni]);
                }
        }
        __syncthreads();
        if (c + 2 < NC) load_chunk(c + 2);
        cp_commit();
    }

    // ------------------------- epilogue -------------------------
    const int rbase = m0 + warp_m * 64 + (lane >> 2);
    const int cbase = n0 + warp_n * 32 + (lane & 3) * 2;
#pragma unroll
    for (int mi = 0; mi < 4; mi++) {
#pragma unroll
        for (int half = 0; half < 2; half++) {
            const int row = rbase + mi * 16 + half * 8;
#pragma unroll
            for (int ni = 0; ni < 4; ni++) {
                const int col = cbase + ni * 8;
                float v0 = acc[mi][ni][half * 2 + 0];
                float v1 = acc[mi][ni][half * 2 + 1];
                if (bias) {
                    v0 += __ldg(&bias[col]);
                    v1 += __ldg(&bias[col + 1]);
                }
                if (GELU) {
                    float x3 = v0 * v0 * v0;
                    v0 = 0.5f * v0 * (1.0f + tanhf(0.7978845608028654f * (v0 + 0.044715f * x3)));
                    x3 = v1 * v1 * v1;
                    v1 = 0.5f * v1 * (1.0f + tanhf(0.7978845608028654f * (v1 + 0.044715f * x3)));
                }
                const size_t o = (size_t)z * cBS + (size_t)row * 512 + col;
                if (RES) {
                    float2 q = *(const float2*)(resp + o);
                    v0 += q.x; v1 += q.y;
                }
                if (WF32)
                    *(float2*)(C + o) = make_float2(v0, v1);
                if (WHILO) {
                    float h0 = __bfloat162float(__float2bfloat16(v0));
                    float h1 = __bfloat162float(__float2bfloat16(v1));
                    *(uint32_t*)(Ch + o) = pack_bf2(v0, v1);
                    *(uint32_t*)(Cl + o) = pack_bf2(v0 - h0, v1 - h1);
                }
            }
        }
    }
}

// ------------------------- prep / elementwise kernels ----------------------
__global__ void k_tsplit(const float* __restrict__ src, bf16* __restrict__ dh,
                         bf16* __restrict__ dl, int R, int C, size_t sBS, size_t dBS)
{
    __shared__ float tile[32][33];
    const int tx = threadIdx.x, ty = threadIdx.y;
    const int c0 = blockIdx.x * 32, r0 = blockIdx.y * 32;
    const int z = blockIdx.z;
    src += (size_t)z * sBS; dh += (size_t)z * dBS; dl += (size_t)z * dBS;
#pragma unroll
    for (int i = 0; i < 4; i++)
        tile[ty + i * 8][tx] = src[(size_t)(r0 + ty + i * 8) * C + c0 + tx];
    __syncthreads();
#pragma unroll
    for (int i = 0; i < 4; i++) {
        float v = tile[tx][ty + i * 8];
        bf16 h = __float2bfloat16(v);
        size_t o = (size_t)(c0 + ty + i * 8) * R + r0 + tx;
        dh[o] = h;
        dl[o] = __float2bfloat16(v - __bfloat162float(h));
    }
}

__global__ void k_rbf_split(const float* __restrict__ pos, const float* __restrict__ sigma,
                            bf16* __restrict__ kh, bf16* __restrict__ kl)
{
    size_t lin = (size_t)blockIdx.x * 256 + threadIdx.x; // < 16*512*512
    int t4 = (int)(lin & 511);
    int m = (int)((lin >> 9) & 511);
    int b = (int)(lin >> 18);
    float s = __ldg(sigma);
    float inv = 1.0f / (2.0f * s * s);
    float gm = (float)m * (1.0f / 511.0f);
    float4 p = *(const float4*)(pos + (size_t)b * Nn + t4 * 4);
    float v0 = __expf(-(gm - p.x) * (gm - p.x) * inv);
    float v1 = __expf(-(gm - p.y) * (gm - p.y) * inv);
    float v2 = __expf(-(gm - p.z) * (gm - p.z) * inv);
    float v3 = __expf(-(gm - p.w) * (gm - p.w) * inv);
    size_t o = ((size_t)b * 512 + m) * 2048 + t4 * 4;
    uint2 hh, ll;
    hh.x = pack_bf2(v0, v1); hh.y = pack_bf2(v2, v3);
    float h0 = __bfloat162float(__float2bfloat16(v0));
    float h1 = __bfloat162float(__float2bfloat16(v1));
    float h2 = __bfloat162float(__float2bfloat16(v2));
    float h3 = __bfloat162float(__float2bfloat16(v3));
    ll.x = pack_bf2(v0 - h0, v1 - h1); ll.y = pack_bf2(v2 - h2, v3 - h3);
    *(uint2*)(kh + o) = hh;
    *(uint2*)(kl + o) = ll;
}

__global__ void k_headmix_split(const float* __restrict__ alpha,
                                const float* __restrict__ field,
                                bf16* __restrict__ oh, bf16* __restrict__ ol)
{
    size_t i2 = (size_t)blockIdx.x * 256 + threadIdx.x; // < 8192*512/2
    size_t idx = i2 * 2;
    int dcol = (int)(idx & 511);
    int h = dcol >> 6, dd = dcol & 63;
    size_t base = idx - dcol;
    float s0 = 0.0f, s1 = 0.0f;
#pragma unroll
    for (int k = 0; k < 8; k++) {
        float a = __ldg(&alpha[h * 8 + k]);
        const float* f = field + base + k * 64 + dd;
        s0 = fmaf(a, f[0], s0);
        s1 = fmaf(a, f[1], s1);
    }
    float h0 = __bfloat162float(__float2bfloat16(s0));
    float h1 = __bfloat162float(__float2bfloat16(s1));
    *(uint32_t*)(oh + idx) = pack_bf2(s0, s1);
    *(uint32_t*)(ol + idx) = pack_bf2(s0 - h0, s1 - h1);
}

template <bool HILO>
__global__ __launch_bounds__(256)
void k_diffuse3(const float* __restrict__ in, float* __restrict__ out,
                const float* __restrict__ coef,
                bf16* __restrict__ oh, bf16* __restrict__ ol)
{
    __shared__ float s[512 * 8];
    const int t = threadIdx.x;
    const int b = blockIdx.x >> 6;
    const int d0 = (blockIdx.x & 63) * 8;
    const int dl = t & 7;
    const size_t gbase = ((size_t)b * Mm) * Dd + d0;
    const float c = DT_C * __ldg(&coef[d0 + dl]);
#pragma unroll
    for (int i = 0; i < 16; i++) {
        int idx = t + i * 256;
        s[idx] = in[gbase + (size_t)(idx >> 3) * Dd + dl];
    }
    __syncthreads();
#pragma unroll
    for (int step = 0; step < 3; step++) {
        float nv[16];
#pragma unroll
        for (int i = 0; i < 16; i++) {
            int idx = t + i * 256;
            int m = idx >> 3;
            float v = s[idx];
            float l = (m > 0) ? s[idx - 8] : v;
            float r = (m < 511) ? s[idx + 8] : v;
            nv[i] = fmaf(c, l + r - 2.0f * v, v);
        }
        __syncthreads();
#pragma unroll
        for (int i = 0; i < 16; i++) s[t + i * 256] = nv[i];
        __syncthreads();
    }
#pragma unroll
    for (int i = 0; i < 16; i++) {
        int idx = t + i * 256;
        size_t g = gbase + (size_t)(idx >> 3) * Dd + dl;
        float v = s[idx];
        out[g] = v;
        if (HILO) {
            bf16 h = __float2bfloat16(v);
            oh[g] = h;
            ol[g] = __float2bfloat16(v - __bfloat162float(h));
        }
    }
}

__global__ __launch_bounds__(128)
void k_sample_ln(const float* __restrict__ pos, const float* __restrict__ emb,
                 const float* __restrict__ field,
                 const float* __restrict__ gam, const float* __restrict__ bet,
                 float* __restrict__ enh, bf16* __restrict__ oh, bf16* __restrict__ ol)
{
    __shared__ float ssum[4], ssq[4], sstat[2];
    int row = blockIdx.x;
    int b = row >> 11;
    float p = __ldg(&pos[row]);
    float u = fminf(fmaxf(p, 0.0f), 1.0f) * (float)(Mm - 1);
    int i0 = (int)u;
    if (i0 > Mm - 2) i0 = Mm - 2;
    float w = u - (float)i0;

    const float* f0 = field + ((size_t)b * Mm + i0) * Dd;
    int t = threadIdx.x;
    int d0 = t * 4;
    float4 a = *(const float4*)(f0 + d0);
    float4 bb = *(const float4*)(f0 + Dd + d0);
    float4 e = *(const float4*)(emb + (size_t)row * Dd + d0);
    float x[4];
    x[0] = fmaf(w, bb.x - a.x, a.x) + e.x;
    x[1] = fmaf(w, bb.y - a.y, a.y) + e.y;
    x[2] = fmaf(w, bb.z - a.z, a.z) + e.z;
    x[3] = fmaf(w, bb.w - a.w, a.w) + e.w;
    float sum = x[0] + x[1] + x[2] + x[3];
    float sq = fmaf(x[0], x[0], fmaf(x[1], x[1], fmaf(x[2], x[2], x[3] * x[3])));
#pragma unroll
    for (int o = 16; o > 0; o >>= 1) {
        sum += __shfl_down_sync(0xffffffffu, sum, o);
        sq += __shfl_down_sync(0xffffffffu, sq, o);
    }
    int wd = t >> 5, ln = t & 31;
    if (ln == 0) { ssum[wd] = sum; ssq[wd] = sq; }
    __syncthreads();
    if (t == 0) {
        float S = ssum[0] + ssum[1] + ssum[2] + ssum[3];
        float Q = ssq[0] + ssq[1] + ssq[2] + ssq[3];
        float mu = S * (1.0f / Dd);
        float var = Q * (1.0f / Dd) - mu * mu;
        sstat[0] = mu;
        sstat[1] = rsqrtf(var + 1e-5f);
    }
    __syncthreads();
    float mu = sstat[0], inv = sstat[1];
    float4 g = *(const float4*)(gam + d0);
    float4 be = *(const float4*)(bet + d0);
    float y[4];
    y[0] = (x[0] - mu) * inv * g.x + be.x;
    y[1] = (x[1] - mu) * inv * g.y + be.y;
    y[2] = (x[2] - mu) * inv * g.z + be.z;
    y[3] = (x[3] - mu) * inv * g.w + be.w;
    size_t o = (size_t)row * Dd + d0;
    *(float4*)(enh + o) = make_float4(y[0], y[1], y[2], y[3]);
    uint2 hh, ll;
    hh.x = pack_bf2(y[0], y[1]); hh.y = pack_bf2(y[2], y[3]);
    float h0 = __bfloat162float(__float2bfloat16(y[0]));
    float h1 = __bfloat162float(__float2bfloat16(y[1]));
    float h2 = __bfloat162float(__float2bfloat16(y[2]));
    float h3 = __bfloat162float(__float2bfloat16(y[3]));
    ll.x = pack_bf2(y[0] - h0, y[1] - h1); ll.y = pack_bf2(y[2] - h2, y[3] - h3);
    *(uint2*)(oh + o) = hh;
    *(uint2*)(ol + o) = ll;
}

__global__ __launch_bounds__(128)
void k_ln2(const float* __restrict__ enh, const float* __restrict__ gam,
           const float* __restrict__ bet, float* __restrict__ out)
{
    __shared__ float ssum[4], ssq[4], sstat[2];
    int row = blockIdx.x;
    int t = threadIdx.x;
    int d0 = t * 4;
    size_t o = (size_t)row * Dd + d0;
    float4 a = *(const float4*)(out + o);
    float4 e = *(const float4*)(enh + o);
    float x[4] = {a.x + e.x, a.y + e.y, a.z + e.z, a.w + e.w};
    float sum = x[0] + x[1] + x[2] + x[3];
    float sq = fmaf(x[0], x[0], fmaf(x[1], x[1], fmaf(x[2], x[2], x[3] * x[3])));
#pragma unroll
    for (int s = 16; s > 0; s >>= 1) {
        sum += __shfl_down_sync(0xffffffffu, sum, s);
        sq += __shfl_down_sync(0xffffffffu, sq, s);
    }
    int wd = t >> 5, ln = t & 31;
    if (ln == 0) { ssum[wd] = sum; ssq[wd] = sq; }
    __syncthreads();
    if (t == 0) {
        float S = ssum[0] + ssum[1] + ssum[2] + ssum[3];
        float Q = ssq[0] + ssq[1] + ssq[2] + ssq[3];
        float mu = S * (1.0f / Dd);
        float var = Q * (1.0f / Dd) - mu * mu;
        sstat[0] = mu;
        sstat[1] = rsqrtf(var + 1e-5f);
    }
    __syncthreads();
    float mu = sstat[0], inv = sstat[1];
    float4 g = *(const float4*)(gam + d0);
    float4 be = *(const float4*)(bet + d0);
    *(float4*)(out + o) = make_float4(
        (x[0] - mu) * inv * g.x + be.x, (x[1] - mu) * inv * g.y + be.y,
        (x[2] - mu) * inv * g.z + be.z, (x[3] - mu) * inv * g.w + be.w);
}

// ---------------------------------------------------------------------------
extern "C" void kernel_launch(void* const* d_in, const int* in_sizes, int n_in,
                              void* d_out, int out_size)
{
    const float* emb   = (const float*)d_in[0];
    const float* pos   = (const float*)d_in[1];
    const float* sigma = (const float*)d_in[2];
    const float* alpha = (const float*)d_in[3];
    const float* w_int = (const float*)d_in[4];
    const float* b_int = (const float*)d_in[5];
    const float* dcoef = (const float*)d_in[6];
    const float* W1    = (const float*)d_in[7];
    const float* b1    = (const float*)d_in[8];
    const float* W2    = (const float*)d_in[9];
    const float* b2    = (const float*)d_in[10];
    const float* ecoef = (const float*)d_in[11];
    const float* ln1g  = (const float*)d_in[12];
    const float* ln1b  = (const float*)d_in[13];
    const float* Wout  = (const float*)d_in[14];
    const float* bout  = (const float*)d_in[15];
    const float* ln2g  = (const float*)d_in[16];
    const float* ln2b  = (const float*)d_in[17];
    float* out = (float*)d_out;

    bf16 *h1, *l1, *h2, *l2, *ebh, *ebl, *wh, *wl;
    float *field, *tmp2, *enh;
    cudaGetSymbolAddress((void**)&h1, g_h1);
    cudaGetSymbolAddress((void**)&l1, g_l1);
    cudaGetSymbolAddress((void**)&h2, g_h2);
    cudaGetSymbolAddress((void**)&l2, g_l2);
    cudaGetSymbolAddress((void**)&ebh, g_ebh);
    cudaGetSymbolAddress((void**)&ebl, g_ebl);
    cudaGetSymbolAddress((void**)&wh, g_wh);
    cudaGetSymbolAddress((void**)&wl, g_wl);
    cudaGetSymbolAddress((void**)&field, g_field);
    cudaGetSymbolAddress((void**)&tmp2, g_tmp2);
    cudaGetSymbolAddress((void**)&enh, g_enh);

    cudaFuncSetAttribute(k_gemm_mma<false, false, true, false>,
                         cudaFuncAttributeMaxDynamicSharedMemorySize, SMEM_SZ);
    cudaFuncSetAttribute(k_gemm_mma<false, true, true, false>,
                         cudaFuncAttributeMaxDynamicSharedMemorySize, SMEM_SZ);
    cudaFuncSetAttribute(k_gemm_mma<true, false, false, true>,
                         cudaFuncAttributeMaxDynamicSharedMemorySize, SMEM_SZ);

    dim3 tT(32, 8);

    // weights^T hi/lo
    k_tsplit<<<dim3(16, 16, 1), tT>>>(w_int, wh + 0 * 262144, wl + 0 * 262144, 512, 512, 0, 0);
    k_tsplit<<<dim3(16, 16, 1), tT>>>(W1,    wh + 1 * 262144, wl + 1 * 262144, 512, 512, 0, 0);
    k_tsplit<<<dim3(16, 16, 1), tT>>>(W2,    wh + 2 * 262144, wl + 2 * 262144, 512, 512, 0, 0);
    k_tsplit<<<dim3(16, 16, 1), tT>>>(Wout,  wh + 3 * 262144, wl + 3 * 262144, 512, 512, 0, 0);

    // embT hi/lo  [b, d, t]
    k_tsplit<<<dim3(16, 64, 16), tT>>>(emb, ebh, ebl, Nn, Dd,
                                       (size_t)Nn * Dd, (size_t)Dd * Nn);

    // K-RBF hi/lo into h1/l1 (flat 16x512x2048)
    k_rbf_split<<<16384, 256>>>(pos, sigma, h1, l1);

    // 1) field = K @ emb^T'   (batched, Kdim=2048)
    k_gemm_mma<false, false, true, false><<<dim3(4, 4, 16), 256, SMEM_SZ>>>(
        h1, l1, 2048, (size_t)512 * 2048,
        ebh, ebl, 2048, (size_t)512 * 2048,
        nullptr, nullptr, field, nullptr, nullptr, (size_t)512 * 512, 2048);

    // 2) head mixing -> h1/l1
    k_headmix_split<<<8192, 256>>>(alpha, field, h1, l1);

    // 3) tmp2 = field + mix @ w_int + b_int
    k_gemm_mma<false, true, true, false><<<dim3(64, 4, 1), 256, SMEM_SZ>>>(
        h1, l1, 512, 0, wh + 0 * 262144, wl + 0 * 262144, 512, 0,
        b_int, field, tmp2, nullptr, nullptr, 0, 512);

    // 4) diffusion x3 -> field (+ hi/lo)
    k_diffuse3<true><<<Bn * 64, 256>>>(tmp2, field, dcoef, h1, l1);

    // 5) gelu(field @ W1 + b1) -> h2/l2 (bf16 only)
    k_gemm_mma<true, false, false, true><<<dim3(64, 4, 1), 256, SMEM_SZ>>>(
        h1, l1, 512, 0, wh + 1 * 262144, wl + 1 * 262144, 512, 0,
        b1, nullptr, nullptr, h2, l2, 0, 512);

    // 6) tmp2 = field + gelu @ W2 + b2
    k_gemm_mma<false, true, true, false><<<dim3(64, 4, 1), 256, SMEM_SZ>>>(
        h2, l2, 512, 0, wh + 2 * 262144, wl + 2 * 262144, 512, 0,
        b2, field, tmp2, nullptr, nullptr, 0, 512);

    // 7) diffusion x3 -> field
    k_diffuse3<false><<<Bn * 64, 256>>>(tmp2, field, ecoef, nullptr, nullptr);

    // 8) enh = LN1(sample(field) + emb)  (+ hi/lo into h1/l1)
    k_sample_ln<<<Bn * Nn, 128>>>(pos, emb, field, ln1g, ln1b, enh, h1, l1);

    // 9) out = enh @ Wout + bout
    k_gemm_mma<false, false, true, false><<<dim3(256, 4, 1), 256, SMEM_SZ>>>(
        h1, l1, 512, 0, wh + 3 * 262144, wl + 3 * 262144, 512, 0,
        bout, nullptr, out, nullptr, nullptr, 0, 512);

    // 10) out = LN2(out + enh)
    k_ln2<<<Bn * Nn, 128>>>(enh, ln2g, ln2b, out);
}

// round 5
// speedup vs baseline: 2.6738x; 1.0071x over previous
#include <cuda_runtime.h>
#include <cuda_bf16.h>
#include <math.h>
#include <stdint.h>

#define Bn 16
#define Nn 2048
#define Dd 512
#define Mm 512
#define DT_C 0.01f

typedef __nv_bfloat16 bf16;

// ------------------------- device scratch (no runtime alloc) ---------------
__device__ bf16 g_h1[(size_t)32768 * 512];   // 32MB  (K-RBF hi / field hi / enh hi)
__device__ bf16 g_l1[(size_t)32768 * 512];   // 32MB
__device__ bf16 g_h2[(size_t)8192 * 512];    // 8MB   (gelu hi)
__device__ bf16 g_l2[(size_t)8192 * 512];    // 8MB
__device__ bf16 g_ebh[(size_t)Bn * Dd * Nn]; // 32MB  embT hi  [b, d, t]
__device__ bf16 g_ebl[(size_t)Bn * Dd * Nn]; // 32MB
__device__ bf16 g_wh[4][512 * 512];          // 2MB   weight^T hi [n, k]
__device__ bf16 g_wl[4][512 * 512];
__device__ float g_field[(size_t)Bn * Mm * Dd]; // 16MB
__device__ float g_tmp2[(size_t)Bn * Mm * Dd];  // 16MB

// ------------------------- helpers -----------------------------------------
__device__ __forceinline__ uint32_t smem_u32(const void* p) {
    uint32_t a;
    asm("{ .reg .u64 t; cvta.to.shared.u64 t, %1; cvt.u32.u64 %0, t; }" : "=r"(a) : "l"(p));
    return a;
}
__device__ __forceinline__ uint32_t pack_bf2(float a, float b) {
    __nv_bfloat162 t = __floats2bfloat162_rn(a, b);
    return *reinterpret_cast<uint32_t*>(&t);
}
__device__ __forceinline__ void cp16(uint32_t dst, const void* src) {
    asm volatile("cp.async.cg.shared.global [%0], [%1], 16;" :: "r"(dst), "l"(src));
}
__device__ __forceinline__ void cp_commit() {
    asm volatile("cp.async.commit_group;");
}
__device__ __forceinline__ void cp_wait2() {
    asm volatile("cp.async.wait_group 2;");
}
__device__ __forceinline__ void ldm_x4(uint32_t* r, uint32_t a) {
    asm volatile("ldmatrix.sync.aligned.m8n8.x4.shared.b16 {%0,%1,%2,%3}, [%4];"
                 : "=r"(r[0]), "=r"(r[1]), "=r"(r[2]), "=r"(r[3]) : "r"(a));
}
__device__ __forceinline__ void ldm_x2(uint32_t* r, uint32_t a) {
    asm volatile("ldmatrix.sync.aligned.m8n8.x2.shared.b16 {%0,%1}, [%2];"
                 : "=r"(r[0]), "=r"(r[1]) : "r"(a));
}
__device__ __forceinline__ void mma_bf16(float* c, const uint32_t* a, const uint32_t* b) {
    asm volatile(
        "mma.sync.aligned.m16n8k16.row.col.f32.bf16.bf16.f32 "
        "{%0,%1,%2,%3}, {%4,%5,%6,%7}, {%8,%9}, {%0,%1,%2,%3};"
        : "+f"(c[0]), "+f"(c[1]), "+f"(c[2]), "+f"(c[3])
        : "r"(a[0]), "r"(a[1]), "r"(a[2]), "r"(a[3]), "r"(b[0]), "r"(b[1]));
}

// ------------------------- HMMA GEMM ----------------------------------------
// D[128,128] CTA tile; A,B hi/lo bf16 K-major ([row][k]); 3-pass hi/lo split.
// SMEM: 3 stages x (Ah,Al,Bh,Bl) x 16KB = 192KB dynamic.
#define STAGE_B 65536u
#define SMEM_SZ (3 * 65536)

template <bool GELU, bool RES, bool WF32, bool WHILO>
__global__ __launch_bounds__(256)
void k_gemm_mma(const bf16* __restrict__ Ah, const bf16* __restrict__ Al,
                size_t aRS, size_t aBS,
                const bf16* __restrict__ Bh, const bf16* __restrict__ Bl,
                size_t bRS, size_t bBS,
                const float* __restrict__ bias, const float* __restrict__ resp,
                float* __restrict__ C, bf16* __restrict__ Ch, bf16* __restrict__ Cl,
                size_t cBS, int Kdim)
{
    extern __shared__ char smem[];
    const uint32_t sb = smem_u32(smem);
    const int t = threadIdx.x;
    const int wid = t >> 5;
    const int lane = t & 31;
    const int warp_m = wid & 1;   // 2 warps over M (64 rows each)
    const int warp_n = wid >> 1;  // 4 warps over N (32 cols each)

    const int m0 = blockIdx.x * 128;
    const int n0 = blockIdx.y * 128;
    const int z = blockIdx.z;

    const bf16* pAh = Ah + (size_t)z * aBS;
    const bf16* pAl = Al + (size_t)z * aBS;
    const bf16* pBh = Bh + (size_t)z * bBS;
    const bf16* pBl = Bl + (size_t)z * bBS;

    const int NC = Kdim >> 6;

    auto load_chunk = [&](int c) {
        const uint32_t buf = sb + (uint32_t)(c % 3) * STAGE_B;
        const int k0 = c << 6;
#pragma unroll
        for (int i = 0; i < 4; i++) {
            int id = t + i * 256;
            int row = id >> 3;
            int seg = id & 7;
            uint32_t soff = (uint32_t)row * 128 + (uint32_t)((seg * 16) ^ ((row & 7) << 4));
            size_t ae = (size_t)(m0 + row) * aRS + k0 + seg * 8;
            size_t be = (size_t)(n0 + row) * bRS + k0 + seg * 8;
            cp16(buf + soff,          pAh + ae);
            cp16(buf + 16384 + soff,  pAl + ae);
            cp16(buf + 32768 + soff,  pBh + be);
            cp16(buf + 49152 + soff,  pBl + be);
        }
    };

    load_chunk(0); cp_commit();
    load_chunk(1); cp_commit();
    load_chunk(2); cp_commit();

    // fragment address precomputation
    const int rowA = warp_m * 64 + (lane & 15);
    const uint32_t maskA = (uint32_t)(rowA & 7) << 4;
    const uint32_t kbA = (uint32_t)(lane >> 4) * 16;
    const int rowB = warp_n * 32 + (lane & 7);
    const uint32_t maskB = (uint32_t)(rowB & 7) << 4;
    const uint32_t kbB = (uint32_t)((lane >> 3) & 1) * 16;

    float acc[4][4][4] = {};

    for (int c = 0; c < NC; c++) {
        cp_wait2();
        __syncthreads();
        const uint32_t buf = sb + (uint32_t)(c % 3) * STAGE_B;
        const uint32_t aBaseH = buf + (uint32_t)rowA * 128;
        const uint32_t aBaseL = aBaseH + 16384;
        const uint32_t bBaseH = buf + 32768 + (uint32_t)rowB * 128;
        const uint32_t bBaseL = bBaseH + 16384;

#pragma unroll
        for (int k16 = 0; k16 < 4; k16++) {
            const uint32_t koffA = ((uint32_t)k16 * 32 + kbA) ^ maskA;
            const uint32_t koffB = ((uint32_t)k16 * 32 + kbB) ^ maskB;
            uint32_t ah[4][4], al[4][4], bh[4][2], bl[4][2];
#pragma unroll
            for (int mi = 0; mi < 4; mi++) {
                ldm_x4(ah[mi], aBaseH + mi * 2048 + koffA);
                ldm_x4(al[mi], aBaseL + mi * 2048 + koffA);
            }
#pragma unroll
            for (int ni = 0; ni < 4; ni++) {
                ldm_x2(bh[ni], bBaseH + ni * 1024 + koffB);
                ldm_x2(bl[ni], bBaseL + ni * 1024 + koffB);
            }
#pragma unroll
            for (int mi = 0; mi < 4; mi++)
#pragma unroll
                for (int ni = 0; ni < 4; ni++) {
                    mma_bf16(acc[mi][ni], ah[mi], bh[ni]);
                    mma_bf16(acc[mi][ni], ah[mi], bl[ni]);
                    mma_bf16(acc[mi][ni], al[mi], bh[ni]);
                }
        }
        __syncthreads();
        if (c + 3 < NC) load_chunk(c + 3);
        cp_commit();
    }

    // ------------------------- epilogue -------------------------
    const int rbase = m0 + warp_m * 64 + (lane >> 2);
    const int cbase = n0 + warp_n * 32 + (lane & 3) * 2;
#pragma unroll
    for (int mi = 0; mi < 4; mi++) {
#pragma unroll
        for (int half = 0; half < 2; half++) {
            const int row = rbase + mi * 16 + half * 8;
#pragma unroll
            for (int ni = 0; ni < 4; ni++) {
                const int col = cbase + ni * 8;
                float v0 = acc[mi][ni][half * 2 + 0];
                float v1 = acc[mi][ni][half * 2 + 1];
                if (bias) {
                    v0 += __ldg(&bias[col]);
                    v1 += __ldg(&bias[col + 1]);
                }
                if (GELU) {
                    float x3 = v0 * v0 * v0;
                    v0 = 0.5f * v0 * (1.0f + tanhf(0.7978845608028654f * (v0 + 0.044715f * x3)));
                    x3 = v1 * v1 * v1;
                    v1 = 0.5f * v1 * (1.0f + tanhf(0.7978845608028654f * (v1 + 0.044715f * x3)));
                }
                const size_t o = (size_t)z * cBS + (size_t)row * 512 + col;
                if (RES) {
                    float2 q = *(const float2*)(resp + o);
                    v0 += q.x; v1 += q.y;
                }
                if (WF32)
                    *(float2*)(C + o) = make_float2(v0, v1);
                if (WHILO) {
                    float h0 = __bfloat162float(__float2bfloat16(v0));
                    float h1 = __bfloat162float(__float2bfloat16(v1));
                    *(uint32_t*)(Ch + o) = pack_bf2(v0, v1);
                    *(uint32_t*)(Cl + o) = pack_bf2(v0 - h0, v1 - h1);
                }
            }
        }
    }
}

// ------------------------- prep / elementwise kernels ----------------------
// Transpose + hi/lo split: src [R, C] f32 -> dst [C, R] bf16 (hi, lo)
__global__ void k_tsplit(const float* __restrict__ src, bf16* __restrict__ dh,
                         bf16* __restrict__ dl, int R, int C, size_t sBS, size_t dBS)
{
    __shared__ float tile[32][33];
    const int tx = threadIdx.x, ty = threadIdx.y;
    const int c0 = blockIdx.x * 32, r0 = blockIdx.y * 32;
    const int z = blockIdx.z;
    src += (size_t)z * sBS; dh += (size_t)z * dBS; dl += (size_t)z * dBS;
#pragma unroll
    for (int i = 0; i < 4; i++)
        tile[ty + i * 8][tx] = src[(size_t)(r0 + ty + i * 8) * C + c0 + tx];
    __syncthreads();
#pragma unroll
    for (int i = 0; i < 4; i++) {
        float v = tile[tx][ty + i * 8];
        bf16 h = __float2bfloat16(v);
        size_t o = (size_t)(c0 + ty + i * 8) * R + r0 + tx;
        dh[o] = h;
        dl[o] = __float2bfloat16(v - __bfloat162float(h));
    }
}

// Fused 4-weight transpose+split (one launch, z selects weight)
__global__ void k_tsplit4(const float* __restrict__ s0, const float* __restrict__ s1,
                          const float* __restrict__ s2, const float* __restrict__ s3,
                          bf16* __restrict__ dh, bf16* __restrict__ dl)
{
    __shared__ float tile[32][33];
    const int tx = threadIdx.x, ty = threadIdx.y;
    const int c0 = blockIdx.x * 32, r0 = blockIdx.y * 32;
    const int z = blockIdx.z;
    const float* src = (z == 0) ? s0 : (z == 1) ? s1 : (z == 2) ? s2 : s3;
    dh += (size_t)z * 262144; dl += (size_t)z * 262144;
#pragma unroll
    for (int i = 0; i < 4; i++)
        tile[ty + i * 8][tx] = src[(size_t)(r0 + ty + i * 8) * 512 + c0 + tx];
    __syncthreads();
#pragma unroll
    for (int i = 0; i < 4; i++) {
        float v = tile[tx][ty + i * 8];
        bf16 h = __float2bfloat16(v);
        size_t o = (size_t)(c0 + ty + i * 8) * 512 + r0 + tx;
        dh[o] = h;
        dl[o] = __float2bfloat16(v - __bfloat162float(h));
    }
}

__global__ void k_rbf_split(const float* __restrict__ pos, const float* __restrict__ sigma,
                            bf16* __restrict__ kh, bf16* __restrict__ kl)
{
    size_t lin = (size_t)blockIdx.x * 256 + threadIdx.x; // < 16*512*512
    int t4 = (int)(lin & 511);
    int m = (int)((lin >> 9) & 511);
    int b = (int)(lin >> 18);
    float s = __ldg(sigma);
    float inv = 1.0f / (2.0f * s * s);
    float gm = (float)m * (1.0f / 511.0f);
    float4 p = *(const float4*)(pos + (size_t)b * Nn + t4 * 4);
    float v0 = __expf(-(gm - p.x) * (gm - p.x) * inv);
    float v1 = __expf(-(gm - p.y) * (gm - p.y) * inv);
    float v2 = __expf(-(gm - p.z) * (gm - p.z) * inv);
    float v3 = __expf(-(gm - p.w) * (gm - p.w) * inv);
    size_t o = ((size_t)b * 512 + m) * 2048 + t4 * 4;
    uint2 hh, ll;
    hh.x = pack_bf2(v0, v1); hh.y = pack_bf2(v2, v3);
    float h0 = __bfloat162float(__float2bfloat16(v0));
    float h1 = __bfloat162float(__float2bfloat16(v1));
    float h2 = __bfloat162float(__float2bfloat16(v2));
    float h3 = __bfloat162float(__float2bfloat16(v3));
    ll.x = pack_bf2(v0 - h0, v1 - h1); ll.y = pack_bf2(v2 - h2, v3 - h3);
    *(uint2*)(kh + o) = hh;
    *(uint2*)(kl + o) = ll;
}

__global__ void k_headmix_split(const float* __restrict__ alpha,
                                const float* __restrict__ field,
                                bf16* __restrict__ oh, bf16* __restrict__ ol)
{
    size_t i2 = (size_t)blockIdx.x * 256 + threadIdx.x; // < 8192*512/2
    size_t idx = i2 * 2;
    int dcol = (int)(idx & 511);
    int h = dcol >> 6, dd = dcol & 63;
    size_t base = idx - dcol;
    float s0 = 0.0f, s1 = 0.0f;
#pragma unroll
    for (int k = 0; k < 8; k++) {
        float a = __ldg(&alpha[h * 8 + k]);
        const float* f = field + base + k * 64 + dd;
        s0 = fmaf(a, f[0], s0);
        s1 = fmaf(a, f[1], s1);
    }
    float h0 = __bfloat162float(__float2bfloat16(s0));
    float h1 = __bfloat162float(__float2bfloat16(s1));
    *(uint32_t*)(oh + idx) = pack_bf2(s0, s1);
    *(uint32_t*)(ol + idx) = pack_bf2(s0 - h0, s1 - h1);
}

template <bool HILO>
__global__ __launch_bounds__(256)
void k_diffuse3(const float* __restrict__ in, float* __restrict__ out,
                const float* __restrict__ coef,
                bf16* __restrict__ oh, bf16* __restrict__ ol)
{
    __shared__ float s[512 * 8];
    const int t = threadIdx.x;
    const int b = blockIdx.x >> 6;
    const int d0 = (blockIdx.x & 63) * 8;
    const int dl = t & 7;
    const size_t gbase = ((size_t)b * Mm) * Dd + d0;
    const float c = DT_C * __ldg(&coef[d0 + dl]);
#pragma unroll
    for (int i = 0; i < 16; i++) {
        int idx = t + i * 256;
        s[idx] = in[gbase + (size_t)(idx >> 3) * Dd + dl];
    }
    __syncthreads();
#pragma unroll
    for (int step = 0; step < 3; step++) {
        float nv[16];
#pragma unroll
        for (int i = 0; i < 16; i++) {
            int idx = t + i * 256;
            int m = idx >> 3;
            float v = s[idx];
            float l = (m > 0) ? s[idx - 8] : v;
            float r = (m < 511) ? s[idx + 8] : v;
            nv[i] = fmaf(c, l + r - 2.0f * v, v);
        }
        __syncthreads();
#pragma unroll
        for (int i = 0; i < 16; i++) s[t + i * 256] = nv[i];
        __syncthreads();
    }
#pragma unroll
    for (int i = 0; i < 16; i++) {
        int idx = t + i * 256;
        size_t g = gbase + (size_t)(idx >> 3) * Dd + dl;
        float v = s[idx];
        out[g] = v;
        if (HILO) {
            bf16 h = __float2bfloat16(v);
            oh[g] = h;
            ol[g] = __float2bfloat16(v - __bfloat162float(h));
        }
    }
}

// sample + residual + LN1 -> hi/lo bf16 only (enh reconstructed later)
__global__ __launch_bounds__(128)
void k_sample_ln(const float* __restrict__ pos, const float* __restrict__ emb,
                 const float* __restrict__ field,
                 const float* __restrict__ gam, const float* __restrict__ bet,
                 bf16* __restrict__ oh, bf16* __restrict__ ol)
{
    __shared__ float ssum[4], ssq[4], sstat[2];
    int row = blockIdx.x;
    int b = row >> 11;
    float p = __ldg(&pos[row]);
    float u = fminf(fmaxf(p, 0.0f), 1.0f) * (float)(Mm - 1);
    int i0 = (int)u;
    if (i0 > Mm - 2) i0 = Mm - 2;
    float w = u - (float)i0;

    const float* f0 = field + ((size_t)b * Mm + i0) * Dd;
    int t = threadIdx.x;
    int d0 = t * 4;
    float4 a = *(const float4*)(f0 + d0);
    float4 bb = *(const float4*)(f0 + Dd + d0);
    float4 e = *(const float4*)(emb + (size_t)row * Dd + d0);
    float x[4];
    x[0] = fmaf(w, bb.x - a.x, a.x) + e.x;
    x[1] = fmaf(w, bb.y - a.y, a.y) + e.y;
    x[2] = fmaf(w, bb.z - a.z, a.z) + e.z;
    x[3] = fmaf(w, bb.w - a.w, a.w) + e.w;
    float sum = x[0] + x[1] + x[2] + x[3];
    float sq = fmaf(x[0], x[0], fmaf(x[1], x[1], fmaf(x[2], x[2], x[3] * x[3])));
#pragma unroll
    for (int o = 16; o > 0; o >>= 1) {
        sum += __shfl_down_sync(0xffffffffu, sum, o);
        sq += __shfl_down_sync(0xffffffffu, sq, o);
    }
    int wd = t >> 5, ln = t & 31;
    if (ln == 0) { ssum[wd] = sum; ssq[wd] = sq; }
    __syncthreads();
    if (t == 0) {
        float S = ssum[0] + ssum[1] + ssum[2] + ssum[3];
        float Q = ssq[0] + ssq[1] + ssq[2] + ssq[3];
        float mu = S * (1.0f / Dd);
        float var = Q * (1.0f / Dd) - mu * mu;
        sstat[0] = mu;
        sstat[1] = rsqrtf(var + 1e-5f);
    }
    __syncthreads();
    float mu = sstat[0], inv = sstat[1];
    float4 g = *(const float4*)(gam + d0);
    float4 be = *(const float4*)(bet + d0);
    float y[4];
    y[0] = (x[0] - mu) * inv * g.x + be.x;
    y[1] = (x[1] - mu) * inv * g.y + be.y;
    y[2] = (x[2] - mu) * inv * g.z + be.z;
    y[3] = (x[3] - mu) * inv * g.w + be.w;
    size_t o = (size_t)row * Dd + d0;
    uint2 hh, ll;
    hh.x = pack_bf2(y[0], y[1]); hh.y = pack_bf2(y[2], y[3]);
    float h0 = __bfloat162float(__float2bfloat16(y[0]));
    float h1 = __bfloat162float(__float2bfloat16(y[1]));
    float h2 = __bfloat162float(__float2bfloat16(y[2]));
    float h3 = __bfloat162float(__float2bfloat16(y[3]));
    ll.x = pack_bf2(y[0] - h0, y[1] - h1); ll.y = pack_bf2(y[2] - h2, y[3] - h3);
    *(uint2*)(oh + o) = hh;
    *(uint2*)(ol + o) = ll;
}

// final residual + LN2 in-place on out; enh reconstructed from hi/lo
__global__ __launch_bounds__(128)
void k_ln2(const bf16* __restrict__ eh, const bf16* __restrict__ el,
           const float* __restrict__ gam, const float* __restrict__ bet,
           float* __restrict__ out)
{
    __shared__ float ssum[4], ssq[4], sstat[2];
    int row = blockIdx.x;
    int t = threadIdx.x;
    int d0 = t * 4;
    size_t o = (size_t)row * Dd + d0;
    float4 a = *(const float4*)(out + o);
    uint2 hv = *(const uint2*)(eh + o);
    uint2 lv = *(const uint2*)(el + o);
    __nv_bfloat162 h01 = *reinterpret_cast<__nv_bfloat162*>(&hv.x);
    __nv_bfloat162 h23 = *reinterpret_cast<__nv_bfloat162*>(&hv.y);
    __nv_bfloat162 l01 = *reinterpret_cast<__nv_bfloat162*>(&lv.x);
    __nv_bfloat162 l23 = *reinterpret_cast<__nv_bfloat162*>(&lv.y);
    float e0 = __bfloat162float(h01.x) + __bfloat162float(l01.x);
    float e1 = __bfloat162float(h01.y) + __bfloat162float(l01.y);
    float e2 = __bfloat162float(h23.x) + __bfloat162float(l23.x);
    float e3 = __bfloat162float(h23.y) + __bfloat162float(l23.y);
    float x[4] = {a.x + e0, a.y + e1, a.z + e2, a.w + e3};
    float sum = x[0] + x[1] + x[2] + x[3];
    float sq = fmaf(x[0], x[0], fmaf(x[1], x[1], fmaf(x[2], x[2], x[3] * x[3])));
#pragma unroll
    for (int s = 16; s > 0; s >>= 1) {
        sum += __shfl_down_sync(0xffffffffu, sum, s);
        sq += __shfl_down_sync(0xffffffffu, sq, s);
    }
    int wd = t >> 5, ln = t & 31;
    if (ln == 0) { ssum[wd] = sum; ssq[wd] = sq; }
    __syncthreads();
    if (t == 0) {
        float S = ssum[0] + ssum[1] + ssum[2] + ssum[3];
        float Q = ssq[0] + ssq[1] + ssq[2] + ssq[3];
        float mu = S * (1.0f / Dd);
        float var = Q * (1.0f / Dd) - mu * mu;
        sstat[0] = mu;
        sstat[1] = rsqrtf(var + 1e-5f);
    }
    __syncthreads();
    float mu = sstat[0], inv = sstat[1];
    float4 g = *(const float4*)(gam + d0);
    float4 be = *(const float4*)(bet + d0);
    *(float4*)(out + o) = make_float4(
        (x[0] - mu) * inv * g.x + be.x, (x[1] - mu) * inv * g.y + be.y,
        (x[2] - mu) * inv * g.z + be.z, (x[3] - mu) * inv * g.w + be.w);
}

// ---------------------------------------------------------------------------
extern "C" void kernel_launch(void* const* d_in, const int* in_sizes, int n_in,
                              void* d_out, int out_size)
{
    const float* emb   = (const float*)d_in[0];
    const float* pos   = (const float*)d_in[1];
    const float* sigma = (const float*)d_in[2];
    const float* alpha = (const float*)d_in[3];
    const float* w_int = (const float*)d_in[4];
    const float* b_int = (const float*)d_in[5];
    const float* dcoef = (const float*)d_in[6];
    const float* W1    = (const float*)d_in[7];
    const float* b1    = (const float*)d_in[8];
    const float* W2    = (const float*)d_in[9];
    const float* b2    = (const float*)d_in[10];
    const float* ecoef = (const float*)d_in[11];
    const float* ln1g  = (const float*)d_in[12];
    const float* ln1b  = (const float*)d_in[13];
    const float* Wout  = (const float*)d_in[14];
    const float* bout  = (const float*)d_in[15];
    const float* ln2g  = (const float*)d_in[16];
    const float* ln2b  = (const float*)d_in[17];
    float* out = (float*)d_out;

    bf16 *h1, *l1, *h2, *l2, *ebh, *ebl, *wh, *wl;
    float *field, *tmp2;
    cudaGetSymbolAddress((void**)&h1, g_h1);
    cudaGetSymbolAddress((void**)&l1, g_l1);
    cudaGetSymbolAddress((void**)&h2, g_h2);
    cudaGetSymbolAddress((void**)&l2, g_l2);
    cudaGetSymbolAddress((void**)&ebh, g_ebh);
    cudaGetSymbolAddress((void**)&ebl, g_ebl);
    cudaGetSymbolAddress((void**)&wh, g_wh);
    cudaGetSymbolAddress((void**)&wl, g_wl);
    cudaGetSymbolAddress((void**)&field, g_field);
    cudaGetSymbolAddress((void**)&tmp2, g_tmp2);

    cudaFuncSetAttribute(k_gemm_mma<false, false, true, false>,
                         cudaFuncAttributeMaxDynamicSharedMemorySize, SMEM_SZ);
    cudaFuncSetAttribute(k_gemm_mma<false, true, true, false>,
                         cudaFuncAttributeMaxDynamicSharedMemorySize, SMEM_SZ);
    cudaFuncSetAttribute(k_gemm_mma<true, false, false, true>,
                         cudaFuncAttributeMaxDynamicSharedMemorySize, SMEM_SZ);

    dim3 tT(32, 8);

    // weights^T hi/lo (single fused launch)
    k_tsplit4<<<dim3(16, 16, 4), tT>>>(w_int, W1, W2, Wout, wh, wl);

    // embT hi/lo  [b, d, t]
    k_tsplit<<<dim3(16, 64, 16), tT>>>(emb, ebh, ebl, Nn, Dd,
                                       (size_t)Nn * Dd, (size_t)Dd * Nn);

    // K-RBF hi/lo into h1/l1 (flat 16x512x2048)
    k_rbf_split<<<16384, 256>>>(pos, sigma, h1, l1);

    // 1) field = K @ emb^T'   (batched, Kdim=2048)
    k_gemm_mma<false, false, true, false><<<dim3(4, 4, 16), 256, SMEM_SZ>>>(
        h1, l1, 2048, (size_t)512 * 2048,
        ebh, ebl, 2048, (size_t)512 * 2048,
        nullptr, nullptr, field, nullptr, nullptr, (size_t)512 * 512, 2048);

    // 2) head mixing -> h1/l1
    k_headmix_split<<<8192, 256>>>(alpha, field, h1, l1);

    // 3) tmp2 = field + mix @ w_int + b_int
    k_gemm_mma<false, true, true, false><<<dim3(64, 4, 1), 256, SMEM_SZ>>>(
        h1, l1, 512, 0, wh + 0 * 262144, wl + 0 * 262144, 512, 0,
        b_int, field, tmp2, nullptr, nullptr, 0, 512);

    // 4) diffusion x3 -> field (+ hi/lo)
    k_diffuse3<true><<<Bn * 64, 256>>>(tmp2, field, dcoef, h1, l1);

    // 5) gelu(field @ W1 + b1) -> h2/l2 (bf16 only)
    k_gemm_mma<true, false, false, true><<<dim3(64, 4, 1), 256, SMEM_SZ>>>(
        h1, l1, 512, 0, wh + 1 * 262144, wl + 1 * 262144, 512, 0,
        b1, nullptr, nullptr, h2, l2, 0, 512);

    // 6) tmp2 = field + gelu @ W2 + b2
    k_gemm_mma<false, true, true, false><<<dim3(64, 4, 1), 256, SMEM_SZ>>>(
        h2, l2, 512, 0, wh + 2 * 262144, wl + 2 * 262144, 512, 0,
        b2, field, tmp2, nullptr, nullptr, 0, 512);

    // 7) diffusion x3 -> field
    k_diffuse3<false><<<Bn * 64, 256>>>(tmp2, field, ecoef, nullptr, nullptr);

    // 8) enh = LN1(sample(field) + emb)  -> hi/lo only (h1/l1)
    k_sample_ln<<<Bn * Nn, 128>>>(pos, emb, field, ln1g, ln1b, h1, l1);

    // 9) out = enh @ Wout + bout
    k_gemm_mma<false, false, true, false><<<dim3(256, 4, 1), 256, SMEM_SZ>>>(
        h1, l1, 512, 0, wh + 3 * 262144, wl + 3 * 262144, 512, 0,
        bout, nullptr, out, nullptr, nullptr, 0, 512);

    // 10) out = LN2(out + enh)
    k_ln2<<<Bn * Nn, 128>>>(h1, l1, ln2g, ln2b, out);
}

// round 6
// speedup vs baseline: 2.7229x; 1.0184x over previous
#include <cuda_runtime.h>
#include <cuda_bf16.h>
#include <math.h>
#include <stdint.h>

#define Bn 16
#define Nn 2048
#define Dd 512
#define Mm 512
#define DT_C 0.01f

typedef __nv_bfloat16 bf16;

// ------------------------- device scratch (no runtime alloc) ---------------
__device__ bf16 g_h1[(size_t)32768 * 512];   // 32MB  (K-RBF hi / field hi / enh hi)
__device__ bf16 g_l1[(size_t)32768 * 512];   // 32MB
__device__ bf16 g_h2[(size_t)8192 * 512];    // 8MB   (gelu hi)
__device__ bf16 g_l2[(size_t)8192 * 512];    // 8MB
__device__ bf16 g_ebh[(size_t)Bn * Dd * Nn]; // 32MB  embT hi  [b, d, t]
__device__ bf16 g_ebl[(size_t)Bn * Dd * Nn]; // 32MB
__device__ bf16 g_wh[4][512 * 512];          // 2MB   weight^T hi [n, k]
__device__ bf16 g_wl[4][512 * 512];
__device__ float g_field[(size_t)Bn * Mm * Dd]; // 16MB
__device__ float g_tmp2[(size_t)Bn * Mm * Dd];  // 16MB

// ------------------------- helpers -----------------------------------------
__device__ __forceinline__ uint32_t smem_u32(const void* p) {
    uint32_t a;
    asm("{ .reg .u64 t; cvta.to.shared.u64 t, %1; cvt.u32.u64 %0, t; }" : "=r"(a) : "l"(p));
    return a;
}
__device__ __forceinline__ uint32_t pack_bf2(float a, float b) {
    __nv_bfloat162 t = __floats2bfloat162_rn(a, b);
    return *reinterpret_cast<uint32_t*>(&t);
}
__device__ __forceinline__ void cp16(uint32_t dst, const void* src) {
    asm volatile("cp.async.cg.shared.global [%0], [%1], 16;" :: "r"(dst), "l"(src));
}
__device__ __forceinline__ void cp_commit() {
    asm volatile("cp.async.commit_group;");
}
__device__ __forceinline__ void cp_wait1() {
    asm volatile("cp.async.wait_group 1;");
}
__device__ __forceinline__ void ldm_x4(uint32_t* r, uint32_t a) {
    asm volatile("ldmatrix.sync.aligned.m8n8.x4.shared.b16 {%0,%1,%2,%3}, [%4];"
                 : "=r"(r[0]), "=r"(r[1]), "=r"(r[2]), "=r"(r[3]) : "r"(a));
}
__device__ __forceinline__ void ldm_x2(uint32_t* r, uint32_t a) {
    asm volatile("ldmatrix.sync.aligned.m8n8.x2.shared.b16 {%0,%1}, [%2];"
                 : "=r"(r[0]), "=r"(r[1]) : "r"(a));
}
__device__ __forceinline__ void mma_bf16(float* c, const uint32_t* a, const uint32_t* b) {
    asm volatile(
        "mma.sync.aligned.m16n8k16.row.col.f32.bf16.bf16.f32 "
        "{%0,%1,%2,%3}, {%4,%5,%6,%7}, {%8,%9}, {%0,%1,%2,%3};"
        : "+f"(c[0]), "+f"(c[1]), "+f"(c[2]), "+f"(c[3])
        : "r"(a[0]), "r"(a[1]), "r"(a[2]), "r"(a[3]), "r"(b[0]), "r"(b[1]));
}

// ------------------------- HMMA GEMM ----------------------------------------
// D[128,64] CTA tile; 8 warps as 4(M)x2(N), warp tile 32x32.
// A,B hi/lo bf16 K-major ([row][k]); K chunks of 64; 3-pass hi/lo split.
// SMEM per stage: Ah 16K | Al 16K | Bh 8K | Bl 8K = 48KB; 2 stages = 96KB
// -> 2 CTAs per SM.
#define STAGE_B 49152u
#define SMEM_SZ (2 * 49152)

template <bool GELU, bool RES, bool WF32, bool WHILO>
__global__ __launch_bounds__(256, 2)
void k_gemm_mma(const bf16* __restrict__ Ah, const bf16* __restrict__ Al,
                size_t aRS, size_t aBS,
                const bf16* __restrict__ Bh, const bf16* __restrict__ Bl,
                size_t bRS, size_t bBS,
                const float* __restrict__ bias, const float* __restrict__ resp,
                float* __restrict__ C, bf16* __restrict__ Ch, bf16* __restrict__ Cl,
                size_t cBS, int Kdim)
{
    extern __shared__ char smem[];
    const uint32_t sb = smem_u32(smem);
    const int t = threadIdx.x;
    const int wid = t >> 5;
    const int lane = t & 31;
    const int warp_m = wid & 3;   // 4 warps over M (32 rows each)
    const int warp_n = wid >> 2;  // 2 warps over N (32 cols each)

    const int m0 = blockIdx.x * 128;
    const int n0 = blockIdx.y * 64;
    const int z = blockIdx.z;

    const bf16* pAh = Ah + (size_t)z * aBS;
    const bf16* pAl = Al + (size_t)z * aBS;
    const bf16* pBh = Bh + (size_t)z * bBS;
    const bf16* pBl = Bl + (size_t)z * bBS;

    const int NC = Kdim >> 6;

    auto load_chunk = [&](int c) {
        const uint32_t buf = sb + (uint32_t)(c & 1) * STAGE_B;
        const int k0 = c << 6;
        // A: 128 rows x 8 segs = 1024 items; 4 iters per operand
#pragma unroll
        for (int i = 0; i < 4; i++) {
            int id = t + i * 256;
            int row = id >> 3;
            int seg = id & 7;
            uint32_t soff = (uint32_t)row * 128 + (uint32_t)((seg * 16) ^ ((row & 7) << 4));
            size_t ae = (size_t)(m0 + row) * aRS + k0 + seg * 8;
            cp16(buf + soff,         pAh + ae);
            cp16(buf + 16384 + soff, pAl + ae);
        }
        // B: 64 rows x 8 segs = 512 items; 2 iters per operand
#pragma unroll
        for (int i = 0; i < 2; i++) {
            int id = t + i * 256;
            int row = id >> 3;
            int seg = id & 7;
            uint32_t soff = (uint32_t)row * 128 + (uint32_t)((seg * 16) ^ ((row & 7) << 4));
            size_t be = (size_t)(n0 + row) * bRS + k0 + seg * 8;
            cp16(buf + 32768 + soff, pBh + be);
            cp16(buf + 40960 + soff, pBl + be);
        }
    };

    load_chunk(0); cp_commit();
    if (NC > 1) { load_chunk(1); cp_commit(); }

    // fragment address precomputation
    const int rowA = warp_m * 32 + (lane & 15);
    const uint32_t maskA = (uint32_t)(rowA & 7) << 4;
    const uint32_t kbA = (uint32_t)(lane >> 4) * 16;
    const int rowB = warp_n * 32 + (lane & 7);
    const uint32_t maskB = (uint32_t)(rowB & 7) << 4;
    const uint32_t kbB = (uint32_t)((lane >> 3) & 1) * 16;

    float acc[2][4][4] = {};

    for (int c = 0; c < NC; c++) {
        cp_wait1();
        __syncthreads();
        const uint32_t buf = sb + (uint32_t)(c & 1) * STAGE_B;
        const uint32_t aBaseH = buf + (uint32_t)rowA * 128;
        const uint32_t aBaseL = aBaseH + 16384;
        const uint32_t bBaseH = buf + 32768 + (uint32_t)rowB * 128;
        const uint32_t bBaseL = bBaseH + 8192;

#pragma unroll
        for (int k16 = 0; k16 < 4; k16++) {
            const uint32_t koffA = ((uint32_t)k16 * 32 + kbA) ^ maskA;
            const uint32_t koffB = ((uint32_t)k16 * 32 + kbB) ^ maskB;
            uint32_t ah[2][4], al[2][4], bh[4][2], bl[4][2];
#pragma unroll
            for (int mi = 0; mi < 2; mi++) {
                ldm_x4(ah[mi], aBaseH + mi * 2048 + koffA);
                ldm_x4(al[mi], aBaseL + mi * 2048 + koffA);
            }
#pragma unroll
            for (int ni = 0; ni < 4; ni++) {
                ldm_x2(bh[ni], bBaseH + ni * 1024 + koffB);
                ldm_x2(bl[ni], bBaseL + ni * 1024 + koffB);
            }
#pragma unroll
            for (int mi = 0; mi < 2; mi++)
#pragma unroll
                for (int ni = 0; ni < 4; ni++) {
                    mma_bf16(acc[mi][ni], ah[mi], bh[ni]);
                    mma_bf16(acc[mi][ni], ah[mi], bl[ni]);
                    mma_bf16(acc[mi][ni], al[mi], bh[ni]);
                }
        }
        __syncthreads();
        if (c + 2 < NC) load_chunk(c + 2);
        cp_commit();
    }

    // ------------------------- epilogue -------------------------
    const int rbase = m0 + warp_m * 32 + (lane >> 2);
    const int cbase = n0 + warp_n * 32 + (lane & 3) * 2;
#pragma unroll
    for (int mi = 0; mi < 2; mi++) {
#pragma unroll
        for (int half = 0; half < 2; half++) {
            const int row = rbase + mi * 16 + half * 8;
#pragma unroll
            for (int ni = 0; ni < 4; ni++) {
                const int col = cbase + ni * 8;
                float v0 = acc[mi][ni][half * 2 + 0];
                float v1 = acc[mi][ni][half * 2 + 1];
                if (bias) {
                    v0 += __ldg(&bias[col]);
                    v1 += __ldg(&bias[col + 1]);
                }
                if (GELU) {
                    float x3 = v0 * v0 * v0;
                    v0 = 0.5f * v0 * (1.0f + tanhf(0.7978845608028654f * (v0 + 0.044715f * x3)));
                    x3 = v1 * v1 * v1;
                    v1 = 0.5f * v1 * (1.0f + tanhf(0.7978845608028654f * (v1 + 0.044715f * x3)));
                }
                const size_t o = (size_t)z * cBS + (size_t)row * 512 + col;
                if (RES) {
                    float2 q = *(const float2*)(resp + o);
                    v0 += q.x; v1 += q.y;
                }
                if (WF32)
                    *(float2*)(C + o) = make_float2(v0, v1);
                if (WHILO) {
                    float h0 = __bfloat162float(__float2bfloat16(v0));
                    float h1 = __bfloat162float(__float2bfloat16(v1));
                    *(uint32_t*)(Ch + o) = pack_bf2(v0, v1);
                    *(uint32_t*)(Cl + o) = pack_bf2(v0 - h0, v1 - h1);
                }
            }
        }
    }
}

// ------------------------- prep / elementwise kernels ----------------------
// Transpose + hi/lo split: src [R, C] f32 -> dst [C, R] bf16 (hi, lo)
__global__ void k_tsplit(const float* __restrict__ src, bf16* __restrict__ dh,
                         bf16* __restrict__ dl, int R, int C, size_t sBS, size_t dBS)
{
    __shared__ float tile[32][33];
    const int tx = threadIdx.x, ty = threadIdx.y;
    const int c0 = blockIdx.x * 32, r0 = blockIdx.y * 32;
    const int z = blockIdx.z;
    src += (size_t)z * sBS; dh += (size_t)z * dBS; dl += (size_t)z * dBS;
#pragma unroll
    for (int i = 0; i < 4; i++)
        tile[ty + i * 8][tx] = src[(size_t)(r0 + ty + i * 8) * C + c0 + tx];
    __syncthreads();
#pragma unroll
    for (int i = 0; i < 4; i++) {
        float v = tile[tx][ty + i * 8];
        bf16 h = __float2bfloat16(v);
        size_t o = (size_t)(c0 + ty + i * 8) * R + r0 + tx;
        dh[o] = h;
        dl[o] = __float2bfloat16(v - __bfloat162float(h));
    }
}

// Fused 4-weight transpose+split (one launch, z selects weight)
__global__ void k_tsplit4(const float* __restrict__ s0, const float* __restrict__ s1,
                          const float* __restrict__ s2, const float* __restrict__ s3,
                          bf16* __restrict__ dh, bf16* __restrict__ dl)
{
    __shared__ float tile[32][33];
    const int tx = threadIdx.x, ty = threadIdx.y;
    const int c0 = blockIdx.x * 32, r0 = blockIdx.y * 32;
    const int z = blockIdx.z;
    const float* src = (z == 0) ? s0 : (z == 1) ? s1 : (z == 2) ? s2 : s3;
    dh += (size_t)z * 262144; dl += (size_t)z * 262144;
#pragma unroll
    for (int i = 0; i < 4; i++)
        tile[ty + i * 8][tx] = src[(size_t)(r0 + ty + i * 8) * 512 + c0 + tx];
    __syncthreads();
#pragma unroll
    for (int i = 0; i < 4; i++) {
        float v = tile[tx][ty + i * 8];
        bf16 h = __float2bfloat16(v);
        size_t o = (size_t)(c0 + ty + i * 8) * 512 + r0 + tx;
        dh[o] = h;
        dl[o] = __float2bfloat16(v - __bfloat162float(h));
    }
}

__global__ void k_rbf_split(const float* __restrict__ pos, const float* __restrict__ sigma,
                            bf16* __restrict__ kh, bf16* __restrict__ kl)
{
    size_t lin = (size_t)blockIdx.x * 256 + threadIdx.x; // < 16*512*512
    int t4 = (int)(lin & 511);
    int m = (int)((lin >> 9) & 511);
    int b = (int)(lin >> 18);
    float s = __ldg(sigma);
    float inv = 1.0f / (2.0f * s * s);
    float gm = (float)m * (1.0f / 511.0f);
    float4 p = *(const float4*)(pos + (size_t)b * Nn + t4 * 4);
    float v0 = __expf(-(gm - p.x) * (gm - p.x) * inv);
    float v1 = __expf(-(gm - p.y) * (gm - p.y) * inv);
    float v2 = __expf(-(gm - p.z) * (gm - p.z) * inv);
    float v3 = __expf(-(gm - p.w) * (gm - p.w) * inv);
    size_t o = ((size_t)b * 512 + m) * 2048 + t4 * 4;
    uint2 hh, ll;
    hh.x = pack_bf2(v0, v1); hh.y = pack_bf2(v2, v3);
    float h0 = __bfloat162float(__float2bfloat16(v0));
    float h1 = __bfloat162float(__float2bfloat16(v1));
    float h2 = __bfloat162float(__float2bfloat16(v2));
    float h3 = __bfloat162float(__float2bfloat16(v3));
    ll.x = pack_bf2(v0 - h0, v1 - h1); ll.y = pack_bf2(v2 - h2, v3 - h3);
    *(uint2*)(kh + o) = hh;
    *(uint2*)(kl + o) = ll;
}

__global__ void k_headmix_split(const float* __restrict__ alpha,
                                const float* __restrict__ field,
                                bf16* __restrict__ oh, bf16* __restrict__ ol)
{
    size_t i2 = (size_t)blockIdx.x * 256 + threadIdx.x; // < 8192*512/2
    size_t idx = i2 * 2;
    int dcol = (int)(idx & 511);
    int h = dcol >> 6, dd = dcol & 63;
    size_t base = idx - dcol;
    float s0 = 0.0f, s1 = 0.0f;
#pragma unroll
    for (int k = 0; k < 8; k++) {
        float a = __ldg(&alpha[h * 8 + k]);
        const float* f = field + base + k * 64 + dd;
        s0 = fmaf(a, f[0], s0);
        s1 = fmaf(a, f[1], s1);
    }
    float h0 = __bfloat162float(__float2bfloat16(s0));
    float h1 = __bfloat162float(__float2bfloat16(s1));
    *(uint32_t*)(oh + idx) = pack_bf2(s0, s1);
    *(uint32_t*)(ol + idx) = pack_bf2(s0 - h0, s1 - h1);
}

template <bool HILO>
__global__ __launch_bounds__(256)
void k_diffuse3(const float* __restrict__ in, float* __restrict__ out,
                const float* __restrict__ coef,
                bf16* __restrict__ oh, bf16* __restrict__ ol)
{
    __shared__ float s[512 * 8];
    const int t = threadIdx.x;
    const int b = blockIdx.x >> 6;
    const int d0 = (blockIdx.x & 63) * 8;
    const int dl = t & 7;
    const size_t gbase = ((size_t)b * Mm) * Dd + d0;
    const float c = DT_C * __ldg(&coef[d0 + dl]);
#pragma unroll
    for (int i = 0; i < 16; i++) {
        int idx = t + i * 256;
        s[idx] = in[gbase + (size_t)(idx >> 3) * Dd + dl];
    }
    __syncthreads();
#pragma unroll
    for (int step = 0; step < 3; step++) {
        float nv[16];
#pragma unroll
        for (int i = 0; i < 16; i++) {
            int idx = t + i * 256;
            int m = idx >> 3;
            float v = s[idx];
            float l = (m > 0) ? s[idx - 8] : v;
            float r = (m < 511) ? s[idx + 8] : v;
            nv[i] = fmaf(c, l + r - 2.0f * v, v);
        }
        __syncthreads();
#pragma unroll
        for (int i = 0; i < 16; i++) s[t + i * 256] = nv[i];
        __syncthreads();
    }
#pragma unroll
    for (int i = 0; i < 16; i++) {
        int idx = t + i * 256;
        size_t g = gbase + (size_t)(idx >> 3) * Dd + dl;
        float v = s[idx];
        out[g] = v;
        if (HILO) {
            bf16 h = __float2bfloat16(v);
            oh[g] = h;
            ol[g] = __float2bfloat16(v - __bfloat162float(h));
        }
    }
}

// sample + residual + LN1 -> hi/lo bf16 only (enh reconstructed later)
__global__ __launch_bounds__(128)
void k_sample_ln(const float* __restrict__ pos, const float* __restrict__ emb,
                 const float* __restrict__ field,
                 const float* __restrict__ gam, const float* __restrict__ bet,
                 bf16* __restrict__ oh, bf16* __restrict__ ol)
{
    __shared__ float ssum[4], ssq[4], sstat[2];
    int row = blockIdx.x;
    int b = row >> 11;
    float p = __ldg(&pos[row]);
    float u = fminf(fmaxf(p, 0.0f), 1.0f) * (float)(Mm - 1);
    int i0 = (int)u;
    if (i0 > Mm - 2) i0 = Mm - 2;
    float w = u - (float)i0;

    const float* f0 = field + ((size_t)b * Mm + i0) * Dd;
    int t = threadIdx.x;
    int d0 = t * 4;
    float4 a = *(const float4*)(f0 + d0);
    float4 bb = *(const float4*)(f0 + Dd + d0);
    float4 e = *(const float4*)(emb + (size_t)row * Dd + d0);
    float x[4];
    x[0] = fmaf(w, bb.x - a.x, a.x) + e.x;
    x[1] = fmaf(w, bb.y - a.y, a.y) + e.y;
    x[2] = fmaf(w, bb.z - a.z, a.z) + e.z;
    x[3] = fmaf(w, bb.w - a.w, a.w) + e.w;
    float sum = x[0] + x[1] + x[2] + x[3];
    float sq = fmaf(x[0], x[0], fmaf(x[1], x[1], fmaf(x[2], x[2], x[3] * x[3])));
#pragma unroll
    for (int o = 16; o > 0; o >>= 1) {
        sum += __shfl_down_sync(0xffffffffu, sum, o);
        sq += __shfl_down_sync(0xffffffffu, sq, o);
    }
    int wd = t >> 5, ln = t & 31;
    if (ln == 0) { ssum[wd] = sum; ssq[wd] = sq; }
    __syncthreads();
    if (t == 0) {
        float S = ssum[0] + ssum[1] + ssum[2] + ssum[3];
        float Q = ssq[0] + ssq[1] + ssq[2] + ssq[3];
        float mu = S * (1.0f / Dd);
        float var = Q * (1.0f / Dd) - mu * mu;
        sstat[0] = mu;
        sstat[1] = rsqrtf(var + 1e-5f);
    }
    __syncthreads();
    float mu = sstat[0], inv = sstat[1];
    float4 g = *(const float4*)(gam + d0);
    float4 be = *(const float4*)(bet + d0);
    float y[4];
    y[0] = (x[0] - mu) * inv * g.x + be.x;
    y[1] = (x[1] - mu) * inv * g.y + be.y;
    y[2] = (x[2] - mu) * inv * g.z + be.z;
    y[3] = (x[3] - mu) * inv * g.w + be.w;
    size_t o = (size_t)row * Dd + d0;
    uint2 hh, ll;
    hh.x = pack_bf2(y[0], y[1]); hh.y = pack_bf2(y[2], y[3]);
    float h0 = __bfloat162float(__float2bfloat16(y[0]));
    float h1 = __bfloat162float(__float2bfloat16(y[1]));
    float h2 = __bfloat162float(__float2bfloat16(y[2]));
    float h3 = __bfloat162float(__float2bfloat16(y[3]));
    ll.x = pack_bf2(y[0] - h0, y[1] - h1); ll.y = pack_bf2(y[2] - h2, y[3] - h3);
    *(uint2*)(oh + o) = hh;
    *(uint2*)(ol + o) = ll;
}

// final residual + LN2 in-place on out; enh reconstructed from hi/lo
__global__ __launch_bounds__(128)
void k_ln2(const bf16* __restrict__ eh, const bf16* __restrict__ el,
           const float* __restrict__ gam, const float* __restrict__ bet,
           float* __restrict__ out)
{
    __shared__ float ssum[4], ssq[4], sstat[2];
    int row = blockIdx.x;
    int t = threadIdx.x;
    int d0 = t * 4;
    size_t o = (size_t)row * Dd + d0;
    float4 a = *(const float4*)(out + o);
    uint2 hv = *(const uint2*)(eh + o);
    uint2 lv = *(const uint2*)(el + o);
    __nv_bfloat162 h01 = *reinterpret_cast<__nv_bfloat162*>(&hv.x);
    __nv_bfloat162 h23 = *reinterpret_cast<__nv_bfloat162*>(&hv.y);
    __nv_bfloat162 l01 = *reinterpret_cast<__nv_bfloat162*>(&lv.x);
    __nv_bfloat162 l23 = *reinterpret_cast<__nv_bfloat162*>(&lv.y);
    float e0 = __bfloat162float(h01.x) + __bfloat162float(l01.x);
    float e1 = __bfloat162float(h01.y) + __bfloat162float(l01.y);
    float e2 = __bfloat162float(h23.x) + __bfloat162float(l23.x);
    float e3 = __bfloat162float(h23.y) + __bfloat162float(l23.y);
    float x[4] = {a.x + e0, a.y + e1, a.z + e2, a.w + e3};
    float sum = x[0] + x[1] + x[2] + x[3];
    float sq = fmaf(x[0], x[0], fmaf(x[1], x[1], fmaf(x[2], x[2], x[3] * x[3])));
#pragma unroll
    for (int s = 16; s > 0; s >>= 1) {
        sum += __shfl_down_sync(0xffffffffu, sum, s);
        sq += __shfl_down_sync(0xffffffffu, sq, s);
    }
    int wd = t >> 5, ln = t & 31;
    if (ln == 0) { ssum[wd] = sum; ssq[wd] = sq; }
    __syncthreads();
    if (t == 0) {
        float S = ssum[0] + ssum[1] + ssum[2] + ssum[3];
        float Q = ssq[0] + ssq[1] + ssq[2] + ssq[3];
        float mu = S * (1.0f / Dd);
        float var = Q * (1.0f / Dd) - mu * mu;
        sstat[0] = mu;
        sstat[1] = rsqrtf(var + 1e-5f);
    }
    __syncthreads();
    float mu = sstat[0], inv = sstat[1];
    float4 g = *(const float4*)(gam + d0);
    float4 be = *(const float4*)(bet + d0);
    *(float4*)(out + o) = make_float4(
        (x[0] - mu) * inv * g.x + be.x, (x[1] - mu) * inv * g.y + be.y,
        (x[2] - mu) * inv * g.z + be.z, (x[3] - mu) * inv * g.w + be.w);
}

// ---------------------------------------------------------------------------
extern "C" void kernel_launch(void* const* d_in, const int* in_sizes, int n_in,
                              void* d_out, int out_size)
{
    const float* emb   = (const float*)d_in[0];
    const float* pos   = (const float*)d_in[1];
    const float* sigma = (const float*)d_in[2];
    const float* alpha = (const float*)d_in[3];
    const float* w_int = (const float*)d_in[4];
    const float* b_int = (const float*)d_in[5];
    const float* dcoef = (const float*)d_in[6];
    const float* W1    = (const float*)d_in[7];
    const float* b1    = (const float*)d_in[8];
    const float* W2    = (const float*)d_in[9];
    const float* b2    = (const float*)d_in[10];
    const float* ecoef = (const float*)d_in[11];
    const float* ln1g  = (const float*)d_in[12];
    const float* ln1b  = (const float*)d_in[13];
    const float* Wout  = (const float*)d_in[14];
    const float* bout  = (const float*)d_in[15];
    const float* ln2g  = (const float*)d_in[16];
    const float* ln2b  = (const float*)d_in[17];
    float* out = (float*)d_out;

    bf16 *h1, *l1, *h2, *l2, *ebh, *ebl, *wh, *wl;
    float *field, *tmp2;
    cudaGetSymbolAddress((void**)&h1, g_h1);
    cudaGetSymbolAddress((void**)&l1, g_l1);
    cudaGetSymbolAddress((void**)&h2, g_h2);
    cudaGetSymbolAddress((void**)&l2, g_l2);
    cudaGetSymbolAddress((void**)&ebh, g_ebh);
    cudaGetSymbolAddress((void**)&ebl, g_ebl);
    cudaGetSymbolAddress((void**)&wh, g_wh);
    cudaGetSymbolAddress((void**)&wl, g_wl);
    cudaGetSymbolAddress((void**)&field, g_field);
    cudaGetSymbolAddress((void**)&tmp2, g_tmp2);

    cudaFuncSetAttribute(k_gemm_mma<false, false, true, false>,
                         cudaFuncAttributeMaxDynamicSharedMemorySize, SMEM_SZ);
    cudaFuncSetAttribute(k_gemm_mma<false, true, true, false>,
                         cudaFuncAttributeMaxDynamicSharedMemorySize, SMEM_SZ);
    cudaFuncSetAttribute(k_gemm_mma<true, false, false, true>,
                         cudaFuncAttributeMaxDynamicSharedMemorySize, SMEM_SZ);

    dim3 tT(32, 8);

    // weights^T hi/lo (single fused launch)
    k_tsplit4<<<dim3(16, 16, 4), tT>>>(w_int, W1, W2, Wout, wh, wl);

    // embT hi/lo  [b, d, t]
    k_tsplit<<<dim3(16, 64, 16), tT>>>(emb, ebh, ebl, Nn, Dd,
                                       (size_t)Nn * Dd, (size_t)Dd * Nn);

    // K-RBF hi/lo into h1/l1 (flat 16x512x2048)
    k_rbf_split<<<16384, 256>>>(pos, sigma, h1, l1);

    // 1) field = K @ emb^T'   (batched, Kdim=2048)
    k_gemm_mma<false, false, true, false><<<dim3(4, 8, 16), 256, SMEM_SZ>>>(
        h1, l1, 2048, (size_t)512 * 2048,
        ebh, ebl, 2048, (size_t)512 * 2048,
        nullptr, nullptr, field, nullptr, nullptr, (size_t)512 * 512, 2048);

    // 2) head mixing -> h1/l1
    k_headmix_split<<<8192, 256>>>(alpha, field, h1, l1);

    // 3) tmp2 = field + mix @ w_int + b_int
    k_gemm_mma<false, true, true, false><<<dim3(64, 8, 1), 256, SMEM_SZ>>>(
        h1, l1, 512, 0, wh + 0 * 262144, wl + 0 * 262144, 512, 0,
        b_int, field, tmp2, nullptr, nullptr, 0, 512);

    // 4) diffusion x3 -> field (+ hi/lo)
    k_diffuse3<true><<<Bn * 64, 256>>>(tmp2, field, dcoef, h1, l1);

    // 5) gelu(field @ W1 + b1) -> h2/l2 (bf16 only)
    k_gemm_mma<true, false, false, true><<<dim3(64, 8, 1), 256, SMEM_SZ>>>(
        h1, l1, 512, 0, wh + 1 * 262144, wl + 1 * 262144, 512, 0,
        b1, nullptr, nullptr, h2, l2, 0, 512);

    // 6) tmp2 = field + gelu @ W2 + b2
    k_gemm_mma<false, true, true, false><<<dim3(64, 8, 1), 256, SMEM_SZ>>>(
        h2, l2, 512, 0, wh + 2 * 262144, wl + 2 * 262144, 512, 0,
        b2, field, tmp2, nullptr, nullptr, 0, 512);

    // 7) diffusion x3 -> field
    k_diffuse3<false><<<Bn * 64, 256>>>(tmp2, field, ecoef, nullptr, nullptr);

    // 8) enh = LN1(sample(field) + emb)  -> hi/lo only (h1/l1)
    k_sample_ln<<<Bn * Nn, 128>>>(pos, emb, field, ln1g, ln1b, h1, l1);

    // 9) out = enh @ Wout + bout
    k_gemm_mma<false, false, true, false><<<dim3(256, 8, 1), 256, SMEM_SZ>>>(
        h1, l1, 512, 0, wh + 3 * 262144, wl + 3 * 262144, 512, 0,
        bout, nullptr, out, nullptr, nullptr, 0, 512);

    // 10) out = LN2(out + enh)
    k_ln2<<<Bn * Nn, 128>>>(h1, l1, ln2g, ln2b, out);
}

// round 7
// speedup vs baseline: 3.4495x; 1.2668x over previous
#include <cuda_runtime.h>
#include <cuda_fp16.h>
#include <math.h>
#include <stdint.h>

#define Bn 16
#define Nn 2048
#define Dd 512
#define Mm 512
#define DT_C 0.01f

typedef __half hf;

// ------------------------- device scratch (no runtime alloc) ---------------
__device__ hf g_h1[(size_t)32768 * 512];   // 32MB  (K-RBF / field / enh hi)
__device__ hf g_l1[(size_t)32768 * 512];   // 32MB  (enh lo for LN2 residual)
__device__ hf g_h2[(size_t)8192 * 512];    // 8MB   (gelu hi)
__device__ hf g_ebh[(size_t)Bn * Dd * Nn]; // 32MB  embT hi  [b, d, t]
__device__ hf g_ebl[(size_t)Bn * Dd * Nn]; // 32MB  embT lo
__device__ hf g_wh[4][512 * 512];          // 2MB   weight^T hi [n, k]
__device__ hf g_wl[4][512 * 512];          // 2MB   weight^T lo
__device__ float g_field[(size_t)Bn * Mm * Dd]; // 16MB
__device__ float g_tmp2[(size_t)Bn * Mm * Dd];  // 16MB

// ------------------------- helpers -----------------------------------------
__device__ __forceinline__ uint32_t smem_u32(const void* p) {
    uint32_t a;
    asm("{ .reg .u64 t; cvta.to.shared.u64 t, %1; cvt.u32.u64 %0, t; }" : "=r"(a) : "l"(p));
    return a;
}
__device__ __forceinline__ uint32_t pack_hf2(float a, float b) {
    __half2 t = __floats2half2_rn(a, b);
    return *reinterpret_cast<uint32_t*>(&t);
}
__device__ __forceinline__ void cp16(uint32_t dst, const void* src) {
    asm volatile("cp.async.cg.shared.global [%0], [%1], 16;" :: "r"(dst), "l"(src));
}
__device__ __forceinline__ void cp_commit() {
    asm volatile("cp.async.commit_group;");
}
__device__ __forceinline__ void cp_wait1() {
    asm volatile("cp.async.wait_group 1;");
}
__device__ __forceinline__ void ldm_x4(uint32_t* r, uint32_t a) {
    asm volatile("ldmatrix.sync.aligned.m8n8.x4.shared.b16 {%0,%1,%2,%3}, [%4];"
                 : "=r"(r[0]), "=r"(r[1]), "=r"(r[2]), "=r"(r[3]) : "r"(a));
}
__device__ __forceinline__ void ldm_x2(uint32_t* r, uint32_t a) {
    asm volatile("ldmatrix.sync.aligned.m8n8.x2.shared.b16 {%0,%1}, [%2];"
                 : "=r"(r[0]), "=r"(r[1]) : "r"(a));
}
__device__ __forceinline__ void mma_f16(float* c, const uint32_t* a, const uint32_t* b) {
    asm volatile(
        "mma.sync.aligned.m16n8k16.row.col.f32.f16.f16.f32 "
        "{%0,%1,%2,%3}, {%4,%5,%6,%7}, {%8,%9}, {%0,%1,%2,%3};"
        : "+f"(c[0]), "+f"(c[1]), "+f"(c[2]), "+f"(c[3])
        : "r"(a[0]), "r"(a[1]), "r"(a[2]), "r"(a[3]), "r"(b[0]), "r"(b[1]));
}

// ------------------------- HMMA GEMM (fp16, 2-pass hi/lo on B) --------------
// D[128,64] CTA tile; 8 warps 4(M)x2(N), warp tile 32x32.
// A single fp16 K-major; B fp16 hi/lo K-major. C = A*Bh + A*Bl.
// SMEM per stage: A 16K | Bh 8K | Bl 8K = 32KB; 2 stages = 64KB -> 2 CTAs/SM.
#define STAGE_B 32768u
#define SMEM_SZ (2 * 32768)

template <bool GELU, bool RES, bool WF32, bool WHALF>
__global__ __launch_bounds__(256, 2)
void k_gemm_mma(const hf* __restrict__ A, size_t aRS, size_t aBS,
                const hf* __restrict__ Bh, const hf* __restrict__ Bl,
                size_t bRS, size_t bBS,
                const float* __restrict__ bias, const float* __restrict__ resp,
                float* __restrict__ C, hf* __restrict__ Ch,
                size_t cBS, int Kdim)
{
    extern __shared__ char smem[];
    const uint32_t sb = smem_u32(smem);
    const int t = threadIdx.x;
    const int wid = t >> 5;
    const int lane = t & 31;
    const int warp_m = wid & 3;   // 4 warps over M (32 rows each)
    const int warp_n = wid >> 2;  // 2 warps over N (32 cols each)

    const int m0 = blockIdx.x * 128;
    const int n0 = blockIdx.y * 64;
    const int z = blockIdx.z;

    const hf* pA  = A  + (size_t)z * aBS;
    const hf* pBh = Bh + (size_t)z * bBS;
    const hf* pBl = Bl + (size_t)z * bBS;

    const int NC = Kdim >> 6;

    auto load_chunk = [&](int c) {
        const uint32_t buf = sb + (uint32_t)(c & 1) * STAGE_B;
        const int k0 = c << 6;
        // A: 128 rows x 8 segs = 1024 items; 4 iters
#pragma unroll
        for (int i = 0; i < 4; i++) {
            int id = t + i * 256;
            int row = id >> 3;
            int seg = id & 7;
            uint32_t soff = (uint32_t)row * 128 + (uint32_t)((seg * 16) ^ ((row & 7) << 4));
            cp16(buf + soff, pA + (size_t)(m0 + row) * aRS + k0 + seg * 8);
        }
        // B: 64 rows x 8 segs = 512 items; 2 iters, two tensors
#pragma unroll
        for (int i = 0; i < 2; i++) {
            int id = t + i * 256;
            int row = id >> 3;
            int seg = id & 7;
            uint32_t soff = (uint32_t)row * 128 + (uint32_t)((seg * 16) ^ ((row & 7) << 4));
            size_t be = (size_t)(n0 + row) * bRS + k0 + seg * 8;
            cp16(buf + 16384 + soff, pBh + be);
            cp16(buf + 24576 + soff, pBl + be);
        }
    };

    load_chunk(0); cp_commit();
    if (NC > 1) { load_chunk(1); cp_commit(); }

    // fragment address precomputation
    const int rowA = warp_m * 32 + (lane & 15);
    const uint32_t maskA = (uint32_t)(rowA & 7) << 4;
    const uint32_t kbA = (uint32_t)(lane >> 4) * 16;
    const int rowB = warp_n * 32 + (lane & 7);
    const uint32_t maskB = (uint32_t)(rowB & 7) << 4;
    const uint32_t kbB = (uint32_t)((lane >> 3) & 1) * 16;

    float acc[2][4][4] = {};

    for (int c = 0; c < NC; c++) {
        cp_wait1();
        __syncthreads();
        const uint32_t buf = sb + (uint32_t)(c & 1) * STAGE_B;
        const uint32_t aBase  = buf + (uint32_t)rowA * 128;
        const uint32_t bBaseH = buf + 16384 + (uint32_t)rowB * 128;
        const uint32_t bBaseL = bBaseH + 8192;

#pragma unroll
        for (int k16 = 0; k16 < 4; k16++) {
            const uint32_t koffA = ((uint32_t)k16 * 32 + kbA) ^ maskA;
            const uint32_t koffB = ((uint32_t)k16 * 32 + kbB) ^ maskB;
            uint32_t ah[2][4], bh[4][2], bl[4][2];
#pragma unroll
            for (int mi = 0; mi < 2; mi++)
                ldm_x4(ah[mi], aBase + mi * 2048 + koffA);
#pragma unroll
            for (int ni = 0; ni < 4; ni++) {
                ldm_x2(bh[ni], bBaseH + ni * 1024 + koffB);
                ldm_x2(bl[ni], bBaseL + ni * 1024 + koffB);
            }
#pragma unroll
            for (int mi = 0; mi < 2; mi++)
#pragma unroll
                for (int ni = 0; ni < 4; ni++) {
                    mma_f16(acc[mi][ni], ah[mi], bh[ni]);
                    mma_f16(acc[mi][ni], ah[mi], bl[ni]);
                }
        }
        __syncthreads();
        if (c + 2 < NC) load_chunk(c + 2);
        cp_commit();
    }

    // ------------------------- epilogue -------------------------
    const int rbase = m0 + warp_m * 32 + (lane >> 2);
    const int cbase = n0 + warp_n * 32 + (lane & 3) * 2;
#pragma unroll
    for (int mi = 0; mi < 2; mi++) {
#pragma unroll
        for (int half = 0; half < 2; half++) {
            const int row = rbase + mi * 16 + half * 8;
#pragma unroll
            for (int ni = 0; ni < 4; ni++) {
                const int col = cbase + ni * 8;
                float v0 = acc[mi][ni][half * 2 + 0];
                float v1 = acc[mi][ni][half * 2 + 1];
                if (bias) {
                    v0 += __ldg(&bias[col]);
                    v1 += __ldg(&bias[col + 1]);
                }
                if (GELU) {
                    float x3 = v0 * v0 * v0;
                    v0 = 0.5f * v0 * (1.0f + tanhf(0.7978845608028654f * (v0 + 0.044715f * x3)));
                    x3 = v1 * v1 * v1;
                    v1 = 0.5f * v1 * (1.0f + tanhf(0.7978845608028654f * (v1 + 0.044715f * x3)));
                }
                const size_t o = (size_t)z * cBS + (size_t)row * 512 + col;
                if (RES) {
                    float2 q = *(const float2*)(resp + o);
                    v0 += q.x; v1 += q.y;
                }
                if (WF32)
                    *(float2*)(C + o) = make_float2(v0, v1);
                if (WHALF)
                    *(uint32_t*)(Ch + o) = pack_hf2(v0, v1);
            }
        }
    }
}

// ------------------------- prep / elementwise kernels ----------------------
// Transpose + fp16 hi/lo split: src [R, C] f32 -> dst [C, R]
__global__ void k_tsplit(const float* __restrict__ src, hf* __restrict__ dh,
                         hf* __restrict__ dl, int R, int C, size_t sBS, size_t dBS)
{
    __shared__ float tile[32][33];
    const int tx = threadIdx.x, ty = threadIdx.y;
    const int c0 = blockIdx.x * 32, r0 = blockIdx.y * 32;
    const int z = blockIdx.z;
    src += (size_t)z * sBS; dh += (size_t)z * dBS; dl += (size_t)z * dBS;
#pragma unroll
    for (int i = 0; i < 4; i++)
        tile[ty + i * 8][tx] = src[(size_t)(r0 + ty + i * 8) * C + c0 + tx];
    __syncthreads();
#pragma unroll
    for (int i = 0; i < 4; i++) {
        float v = tile[tx][ty + i * 8];
        hf h = __float2half_rn(v);
        size_t o = (size_t)(c0 + ty + i * 8) * R + r0 + tx;
        dh[o] = h;
        dl[o] = __float2half_rn(v - __half2float(h));
    }
}

// Fused 4-weight transpose+split (one launch, z selects weight)
__global__ void k_tsplit4(const float* __restrict__ s0, const float* __restrict__ s1,
                          const float* __restrict__ s2, const float* __restrict__ s3,
                          hf* __restrict__ dh, hf* __restrict__ dl)
{
    __shared__ float tile[32][33];
    const int tx = threadIdx.x, ty = threadIdx.y;
    const int c0 = blockIdx.x * 32, r0 = blockIdx.y * 32;
    const int z = blockIdx.z;
    const float* src = (z == 0) ? s0 : (z == 1) ? s1 : (z == 2) ? s2 : s3;
    dh += (size_t)z * 262144; dl += (size_t)z * 262144;
#pragma unroll
    for (int i = 0; i < 4; i++)
        tile[ty + i * 8][tx] = src[(size_t)(r0 + ty + i * 8) * 512 + c0 + tx];
    __syncthreads();
#pragma unroll
    for (int i = 0; i < 4; i++) {
        float v = tile[tx][ty + i * 8];
        hf h = __float2half_rn(v);
        size_t o = (size_t)(c0 + ty + i * 8) * 512 + r0 + tx;
        dh[o] = h;
        dl[o] = __float2half_rn(v - __half2float(h));
    }
}

// K_rbf -> single fp16
__global__ void k_rbf_half(const float* __restrict__ pos, const float* __restrict__ sigma,
                           hf* __restrict__ kh)
{
    size_t lin = (size_t)blockIdx.x * 256 + threadIdx.x; // < 16*512*512
    int t4 = (int)(lin & 511);
    int m = (int)((lin >> 9) & 511);
    int b = (int)(lin >> 18);
    float s = __ldg(sigma);
    float inv = 1.0f / (2.0f * s * s);
    float gm = (float)m * (1.0f / 511.0f);
    float4 p = *(const float4*)(pos + (size_t)b * Nn + t4 * 4);
    float v0 = __expf(-(gm - p.x) * (gm - p.x) * inv);
    float v1 = __expf(-(gm - p.y) * (gm - p.y) * inv);
    float v2 = __expf(-(gm - p.z) * (gm - p.z) * inv);
    float v3 = __expf(-(gm - p.w) * (gm - p.w) * inv);
    size_t o = ((size_t)b * 512 + m) * 2048 + t4 * 4;
    uint2 hh;
    hh.x = pack_hf2(v0, v1); hh.y = pack_hf2(v2, v3);
    *(uint2*)(kh + o) = hh;
}

// Head mixing -> single fp16
__global__ void k_headmix_half(const float* __restrict__ alpha,
                               const float* __restrict__ field,
                               hf* __restrict__ oh)
{
    size_t i2 = (size_t)blockIdx.x * 256 + threadIdx.x; // < 8192*512/2
    size_t idx = i2 * 2;
    int dcol = (int)(idx & 511);
    int h = dcol >> 6, dd = dcol & 63;
    size_t base = idx - dcol;
    float s0 = 0.0f, s1 = 0.0f;
#pragma unroll
    for (int k = 0; k < 8; k++) {
        float a = __ldg(&alpha[h * 8 + k]);
        const float* f = field + base + k * 64 + dd;
        s0 = fmaf(a, f[0], s0);
        s1 = fmaf(a, f[1], s1);
    }
    *(uint32_t*)(oh + idx) = pack_hf2(s0, s1);
}

template <bool HOUT>
__global__ __launch_bounds__(256)
void k_diffuse3(const float* __restrict__ in, float* __restrict__ out,
                const float* __restrict__ coef, hf* __restrict__ oh)
{
    __shared__ float s[512 * 8];
    const int t = threadIdx.x;
    const int b = blockIdx.x >> 6;
    const int d0 = (blockIdx.x & 63) * 8;
    const int dl = t & 7;
    const size_t gbase = ((size_t)b * Mm) * Dd + d0;
    const float c = DT_C * __ldg(&coef[d0 + dl]);
#pragma unroll
    for (int i = 0; i < 16; i++) {
        int idx = t + i * 256;
        s[idx] = in[gbase + (size_t)(idx >> 3) * Dd + dl];
    }
    __syncthreads();
#pragma unroll
    for (int step = 0; step < 3; step++) {
        float nv[16];
#pragma unroll
        for (int i = 0; i < 16; i++) {
            int idx = t + i * 256;
            int m = idx >> 3;
            float v = s[idx];
            float l = (m > 0) ? s[idx - 8] : v;
            float r = (m < 511) ? s[idx + 8] : v;
            nv[i] = fmaf(c, l + r - 2.0f * v, v);
        }
        __syncthreads();
#pragma unroll
        for (int i = 0; i < 16; i++) s[t + i * 256] = nv[i];
        __syncthreads();
    }
#pragma unroll
    for (int i = 0; i < 16; i++) {
        int idx = t + i * 256;
        size_t g = gbase + (size_t)(idx >> 3) * Dd + dl;
        float v = s[idx];
        out[g] = v;
        if (HOUT) oh[g] = __float2half_rn(v);
    }
}

// sample + residual + LN1 -> fp16 hi (GEMM A) + lo (LN2 residual accuracy)
__global__ __launch_bounds__(128)
void k_sample_ln(const float* __restrict__ pos, const float* __restrict__ emb,
                 const float* __restrict__ field,
                 const float* __restrict__ gam, const float* __restrict__ bet,
                 hf* __restrict__ oh, hf* __restrict__ ol)
{
    __shared__ float ssum[4], ssq[4], sstat[2];
    int row = blockIdx.x;
    int b = row >> 11;
    float p = __ldg(&pos[row]);
    float u = fminf(fmaxf(p, 0.0f), 1.0f) * (float)(Mm - 1);
    int i0 = (int)u;
    if (i0 > Mm - 2) i0 = Mm - 2;
    float w = u - (float)i0;

    const float* f0 = field + ((size_t)b * Mm + i0) * Dd;
    int t = threadIdx.x;
    int d0 = t * 4;
    float4 a = *(const float4*)(f0 + d0);
    float4 bb = *(const float4*)(f0 + Dd + d0);
    float4 e = *(const float4*)(emb + (size_t)row * Dd + d0);
    float x[4];
    x[0] = fmaf(w, bb.x - a.x, a.x) + e.x;
    x[1] = fmaf(w, bb.y - a.y, a.y) + e.y;
    x[2] = fmaf(w, bb.z - a.z, a.z) + e.z;
    x[3] = fmaf(w, bb.w - a.w, a.w) + e.w;
    float sum = x[0] + x[1] + x[2] + x[3];
    float sq = fmaf(x[0], x[0], fmaf(x[1], x[1], fmaf(x[2], x[2], x[3] * x[3])));
#pragma unroll
    for (int o = 16; o > 0; o >>= 1) {
        sum += __shfl_down_sync(0xffffffffu, sum, o);
        sq += __shfl_down_sync(0xffffffffu, sq, o);
    }
    int wd = t >> 5, ln = t & 31;
    if (ln == 0) { ssum[wd] = sum; ssq[wd] = sq; }
    __syncthreads();
    if (t == 0) {
        float S = ssum[0] + ssum[1] + ssum[2] + ssum[3];
        float Q = ssq[0] + ssq[1] + ssq[2] + ssq[3];
        float mu = S * (1.0f / Dd);
        float var = Q * (1.0f / Dd) - mu * mu;
        sstat[0] = mu;
        sstat[1] = rsqrtf(var + 1e-5f);
    }
    __syncthreads();
    float mu = sstat[0], inv = sstat[1];
    float4 g = *(const float4*)(gam + d0);
    float4 be = *(const float4*)(bet + d0);
    float y[4];
    y[0] = (x[0] - mu) * inv * g.x + be.x;
    y[1] = (x[1] - mu) * inv * g.y + be.y;
    y[2] = (x[2] - mu) * inv * g.z + be.z;
    y[3] = (x[3] - mu) * inv * g.w + be.w;
    size_t o = (size_t)row * Dd + d0;
    uint2 hh, ll;
    hh.x = pack_hf2(y[0], y[1]); hh.y = pack_hf2(y[2], y[3]);
    float h0 = __half2float(__float2half_rn(y[0]));
    float h1 = __half2float(__float2half_rn(y[1]));
    float h2 = __half2float(__float2half_rn(y[2]));
    float h3 = __half2float(__float2half_rn(y[3]));
    ll.x = pack_hf2(y[0] - h0, y[1] - h1); ll.y = pack_hf2(y[2] - h2, y[3] - h3);
    *(uint2*)(oh + o) = hh;
    *(uint2*)(ol + o) = ll;
}

// final residual + LN2 in-place on out; enh reconstructed from fp16 hi/lo
__global__ __launch_bounds__(128)
void k_ln2(const hf* __restrict__ eh, const hf* __restrict__ el,
           const float* __restrict__ gam, const float* __restrict__ bet,
           float* __restrict__ out)
{
    __shared__ float ssum[4], ssq[4], sstat[2];
    int row = blockIdx.x;
    int t = threadIdx.x;
    int d0 = t * 4;
    size_t o = (size_t)row * Dd + d0;
    float4 a = *(const float4*)(out + o);
    uint2 hv = *(const uint2*)(eh + o);
    uint2 lv = *(const uint2*)(el + o);
    __half2 h01 = *reinterpret_cast<__half2*>(&hv.x);
    __half2 h23 = *reinterpret_cast<__half2*>(&hv.y);
    __half2 l01 = *reinterpret_cast<__half2*>(&lv.x);
    __half2 l23 = *reinterpret_cast<__half2*>(&lv.y);
    float e0 = __half2float(h01.x) + __half2float(l01.x);
    float e1 = __half2float(h01.y) + __half2float(l01.y);
    float e2 = __half2float(h23.x) + __half2float(l23.x);
    float e3 = __half2float(h23.y) + __half2float(l23.y);
    float x[4] = {a.x + e0, a.y + e1, a.z + e2, a.w + e3};
    float sum = x[0] + x[1] + x[2] + x[3];
    float sq = fmaf(x[0], x[0], fmaf(x[1], x[1], fmaf(x[2], x[2], x[3] * x[3])));
#pragma unroll
    for (int s = 16; s > 0; s >>= 1) {
        sum += __shfl_down_sync(0xffffffffu, sum, s);
        sq += __shfl_down_sync(0xffffffffu, sq, s);
    }
    int wd = t >> 5, ln = t & 31;
    if (ln == 0) { ssum[wd] = sum; ssq[wd] = sq; }
    __syncthreads();
    if (t == 0) {
        float S = ssum[0] + ssum[1] + ssum[2] + ssum[3];
        float Q = ssq[0] + ssq[1] + ssq[2] + ssq[3];
        float mu = S * (1.0f / Dd);
        float var = Q * (1.0f / Dd) - mu * mu;
        sstat[0] = mu;
        sstat[1] = rsqrtf(var + 1e-5f);
    }
    __syncthreads();
    float mu = sstat[0], inv = sstat[1];
    float4 g = *(const float4*)(gam + d0);
    float4 be = *(const float4*)(bet + d0);
    *(float4*)(out + o) = make_float4(
        (x[0] - mu) * inv * g.x + be.x, (x[1] - mu) * inv * g.y + be.y,
        (x[2] - mu) * inv * g.z + be.z, (x[3] - mu) * inv * g.w + be.w);
}

// ---------------------------------------------------------------------------
extern "C" void kernel_launch(void* const* d_in, const int* in_sizes, int n_in,
                              void* d_out, int out_size)
{
    const float* emb   = (const float*)d_in[0];
    const float* pos   = (const float*)d_in[1];
    const float* sigma = (const float*)d_in[2];
    const float* alpha = (const float*)d_in[3];
    const float* w_int = (const float*)d_in[4];
    const float* b_int = (const float*)d_in[5];
    const float* dcoef = (const float*)d_in[6];
    const float* W1    = (const float*)d_in[7];
    const float* b1    = (const float*)d_in[8];
    const float* W2    = (const float*)d_in[9];
    const float* b2    = (const float*)d_in[10];
    const float* ecoef = (const float*)d_in[11];
    const float* ln1g  = (const float*)d_in[12];
    const float* ln1b  = (const float*)d_in[13];
    const float* Wout  = (const float*)d_in[14];
    const float* bout  = (const float*)d_in[15];
    const float* ln2g  = (const float*)d_in[16];
    const float* ln2b  = (const float*)d_in[17];
    float* out = (float*)d_out;

    hf *h1, *l1, *h2, *ebh, *ebl, *wh, *wl;
    float *field, *tmp2;
    cudaGetSymbolAddress((void**)&h1, g_h1);
    cudaGetSymbolAddress((void**)&l1, g_l1);
    cudaGetSymbolAddress((void**)&h2, g_h2);
    cudaGetSymbolAddress((void**)&ebh, g_ebh);
    cudaGetSymbolAddress((void**)&ebl, g_ebl);
    cudaGetSymbolAddress((void**)&wh, g_wh);
    cudaGetSymbolAddress((void**)&wl, g_wl);
    cudaGetSymbolAddress((void**)&field, g_field);
    cudaGetSymbolAddress((void**)&tmp2, g_tmp2);

    cudaFuncSetAttribute(k_gemm_mma<false, false, true, false>,
                         cudaFuncAttributeMaxDynamicSharedMemorySize, SMEM_SZ);
    cudaFuncSetAttribute(k_gemm_mma<false, true, true, false>,
                         cudaFuncAttributeMaxDynamicSharedMemorySize, SMEM_SZ);
    cudaFuncSetAttribute(k_gemm_mma<true, false, false, true>,
                         cudaFuncAttributeMaxDynamicSharedMemorySize, SMEM_SZ);

    dim3 tT(32, 8);

    // weights^T fp16 hi/lo (single fused launch)
    k_tsplit4<<<dim3(16, 16, 4), tT>>>(w_int, W1, W2, Wout, wh, wl);

    // embT fp16 hi/lo  [b, d, t]
    k_tsplit<<<dim3(16, 64, 16), tT>>>(emb, ebh, ebl, Nn, Dd,
                                       (size_t)Nn * Dd, (size_t)Dd * Nn);

    // K-RBF single fp16 into h1 (flat 16x512x2048)
    k_rbf_half<<<16384, 256>>>(pos, sigma, h1);

    // 1) field = K @ emb^T'   (batched, Kdim=2048)
    k_gemm_mma<false, false, true, false><<<dim3(4, 8, 16), 256, SMEM_SZ>>>(
        h1, 2048, (size_t)512 * 2048,
        ebh, ebl, 2048, (size_t)512 * 2048,
        nullptr, nullptr, field, nullptr, (size_t)512 * 512, 2048);

    // 2) head mixing -> h1 (single fp16)
    k_headmix_half<<<8192, 256>>>(alpha, field, h1);

    // 3) tmp2 = field + mix @ w_int + b_int
    k_gemm_mma<false, true, true, false><<<dim3(64, 8, 1), 256, SMEM_SZ>>>(
        h1, 512, 0, wh + 0 * 262144, wl + 0 * 262144, 512, 0,
        b_int, field, tmp2, nullptr, 0, 512);

    // 4) diffusion x3 -> field (+ fp16)
    k_diffuse3<true><<<Bn * 64, 256>>>(tmp2, field, dcoef, h1);

    // 5) gelu(field @ W1 + b1) -> h2 (fp16 only)
    k_gemm_mma<true, false, false, true><<<dim3(64, 8, 1), 256, SMEM_SZ>>>(
        h1, 512, 0, wh + 1 * 262144, wl + 1 * 262144, 512, 0,
        b1, nullptr, nullptr, h2, 0, 512);

    // 6) tmp2 = field + gelu @ W2 + b2
    k_gemm_mma<false, true, true, false><<<dim3(64, 8, 1), 256, SMEM_SZ>>>(
        h2, 512, 0, wh + 2 * 262144, wl + 2 * 262144, 512, 0,
        b2, field, tmp2, nullptr, 0, 512);

    // 7) diffusion x3 -> field
    k_diffuse3<false><<<Bn * 64, 256>>>(tmp2, field, ecoef, nullptr);

    // 8) enh = LN1(sample(field) + emb) -> h1 (hi) + l1 (lo)
    k_sample_ln<<<Bn * Nn, 128>>>(pos, emb, field, ln1g, ln1b, h1, l1);

    // 9) out = enh @ Wout + bout
    k_gemm_mma<false, false, true, false><<<dim3(256, 8, 1), 256, SMEM_SZ>>>(
        h1, 512, 0, wh + 3 * 262144, wl + 3 * 262144, 512, 0,
        bout, nullptr, out, nullptr, 0, 512);

    // 10) out = LN2(out + enh)
    k_ln2<<<Bn * Nn, 128>>>(h1, l1, ln2g, ln2b, out);
}

// round 8
// speedup vs baseline: 4.4393x; 1.2870x over previous
#include <cuda_runtime.h>
#include <cuda_fp16.h>
#include <math.h>
#include <stdint.h>

#define Bn 16
#define Nn 2048
#define Dd 512
#define Mm 512
#define DT_C 0.01f

typedef __half hf;

// ------------------------- device scratch (no runtime alloc) ---------------
__device__ hf g_h1[(size_t)32768 * 512];   // 32MB  (K-RBF / field / enh hi)
__device__ hf g_l1[(size_t)32768 * 512];   // 32MB  (enh lo for LN2 residual)
__device__ hf g_h2[(size_t)8192 * 512];    // 8MB   (gelu)
__device__ hf g_ebh[(size_t)Bn * Dd * Nn]; // 32MB  embT  [b, d, t]
__device__ hf g_wh[4][512 * 512];          // 2MB   weight^T [n, k]
__device__ float g_field[(size_t)Bn * Mm * Dd]; // 16MB
__device__ float g_tmp2[(size_t)Bn * Mm * Dd];  // 16MB

// ------------------------- helpers -----------------------------------------
__device__ __forceinline__ uint32_t smem_u32(const void* p) {
    uint32_t a;
    asm("{ .reg .u64 t; cvta.to.shared.u64 t, %1; cvt.u32.u64 %0, t; }" : "=r"(a) : "l"(p));
    return a;
}
__device__ __forceinline__ uint32_t pack_hf2(float a, float b) {
    __half2 t = __floats2half2_rn(a, b);
    return *reinterpret_cast<uint32_t*>(&t);
}
__device__ __forceinline__ void cp16(uint32_t dst, const void* src) {
    asm volatile("cp.async.cg.shared.global [%0], [%1], 16;" :: "r"(dst), "l"(src));
}
__device__ __forceinline__ void cp_commit() {
    asm volatile("cp.async.commit_group;");
}
__device__ __forceinline__ void cp_wait1() {
    asm volatile("cp.async.wait_group 1;");
}
__device__ __forceinline__ void ldm_x4(uint32_t* r, uint32_t a) {
    asm volatile("ldmatrix.sync.aligned.m8n8.x4.shared.b16 {%0,%1,%2,%3}, [%4];"
                 : "=r"(r[0]), "=r"(r[1]), "=r"(r[2]), "=r"(r[3]) : "r"(a));
}
__device__ __forceinline__ void ldm_x2(uint32_t* r, uint32_t a) {
    asm volatile("ldmatrix.sync.aligned.m8n8.x2.shared.b16 {%0,%1}, [%2];"
                 : "=r"(r[0]), "=r"(r[1]) : "r"(a));
}
__device__ __forceinline__ void mma_f16(float* c, const uint32_t* a, const uint32_t* b) {
    asm volatile(
        "mma.sync.aligned.m16n8k16.row.col.f32.f16.f16.f32 "
        "{%0,%1,%2,%3}, {%4,%5,%6,%7}, {%8,%9}, {%0,%1,%2,%3};"
        : "+f"(c[0]), "+f"(c[1]), "+f"(c[2]), "+f"(c[3])
        : "r"(a[0]), "r"(a[1]), "r"(a[2]), "r"(a[3]), "r"(b[0]), "r"(b[1]));
}

// ------------------------- HMMA GEMM (fp16, single-pass) --------------------
// D[128,64] CTA tile; 8 warps 4(M)x2(N), warp tile 32x32.
// A, B single fp16 K-major. SMEM/stage: A 16K | B 8K = 24KB; 2 stages = 48KB.
#define STAGE_B 24576u
#define SMEM_SZ (2 * 24576)

template <bool GELU, bool RES, bool WF32, bool WHALF>
__global__ __launch_bounds__(256, 2)
void k_gemm_mma(const hf* __restrict__ A, size_t aRS, size_t aBS,
                const hf* __restrict__ B, size_t bRS, size_t bBS,
                const float* __restrict__ bias, const float* __restrict__ resp,
                float* __restrict__ C, hf* __restrict__ Ch,
                size_t cBS, int Kdim)
{
    extern __shared__ char smem[];
    const uint32_t sb = smem_u32(smem);
    const int t = threadIdx.x;
    const int wid = t >> 5;
    const int lane = t & 31;
    const int warp_m = wid & 3;   // 4 warps over M (32 rows each)
    const int warp_n = wid >> 2;  // 2 warps over N (32 cols each)

    const int m0 = blockIdx.x * 128;
    const int n0 = blockIdx.y * 64;
    const int z = blockIdx.z;

    const hf* pA = A + (size_t)z * aBS;
    const hf* pB = B + (size_t)z * bBS;

    const int NC = Kdim >> 6;

    auto load_chunk = [&](int c) {
        const uint32_t buf = sb + (uint32_t)(c & 1) * STAGE_B;
        const int k0 = c << 6;
        // A: 128 rows x 8 segs = 1024 items; 4 iters
#pragma unroll
        for (int i = 0; i < 4; i++) {
            int id = t + i * 256;
            int row = id >> 3;
            int seg = id & 7;
            uint32_t soff = (uint32_t)row * 128 + (uint32_t)((seg * 16) ^ ((row & 7) << 4));
            cp16(buf + soff, pA + (size_t)(m0 + row) * aRS + k0 + seg * 8);
        }
        // B: 64 rows x 8 segs = 512 items; 2 iters
#pragma unroll
        for (int i = 0; i < 2; i++) {
            int id = t + i * 256;
            int row = id >> 3;
            int seg = id & 7;
            uint32_t soff = (uint32_t)row * 128 + (uint32_t)((seg * 16) ^ ((row & 7) << 4));
            cp16(buf + 16384 + soff, pB + (size_t)(n0 + row) * bRS + k0 + seg * 8);
        }
    };

    load_chunk(0); cp_commit();
    if (NC > 1) { load_chunk(1); cp_commit(); }

    // fragment address precomputation
    const int rowA = warp_m * 32 + (lane & 15);
    const uint32_t maskA = (uint32_t)(rowA & 7) << 4;
    const uint32_t kbA = (uint32_t)(lane >> 4) * 16;
    const int rowB = warp_n * 32 + (lane & 7);
    const uint32_t maskB = (uint32_t)(rowB & 7) << 4;
    const uint32_t kbB = (uint32_t)((lane >> 3) & 1) * 16;

    float acc[2][4][4] = {};

    for (int c = 0; c < NC; c++) {
        cp_wait1();
        __syncthreads();
        const uint32_t buf = sb + (uint32_t)(c & 1) * STAGE_B;
        const uint32_t aBase = buf + (uint32_t)rowA * 128;
        const uint32_t bBase = buf + 16384 + (uint32_t)rowB * 128;

#pragma unroll
        for (int k16 = 0; k16 < 4; k16++) {
            const uint32_t koffA = ((uint32_t)k16 * 32 + kbA) ^ maskA;
            const uint32_t koffB = ((uint32_t)k16 * 32 + kbB) ^ maskB;
            uint32_t ah[2][4], bh[4][2];
#pragma unroll
            for (int mi = 0; mi < 2; mi++)
                ldm_x4(ah[mi], aBase + mi * 2048 + koffA);
#pragma unroll
            for (int ni = 0; ni < 4; ni++)
                ldm_x2(bh[ni], bBase + ni * 1024 + koffB);
#pragma unroll
            for (int mi = 0; mi < 2; mi++)
#pragma unroll
                for (int ni = 0; ni < 4; ni++)
                    mma_f16(acc[mi][ni], ah[mi], bh[ni]);
        }
        __syncthreads();
        if (c + 2 < NC) load_chunk(c + 2);
        cp_commit();
    }

    // ------------------------- epilogue -------------------------
    const int rbase = m0 + warp_m * 32 + (lane >> 2);
    const int cbase = n0 + warp_n * 32 + (lane & 3) * 2;
#pragma unroll
    for (int mi = 0; mi < 2; mi++) {
#pragma unroll
        for (int half = 0; half < 2; half++) {
            const int row = rbase + mi * 16 + half * 8;
#pragma unroll
            for (int ni = 0; ni < 4; ni++) {
                const int col = cbase + ni * 8;
                float v0 = acc[mi][ni][half * 2 + 0];
                float v1 = acc[mi][ni][half * 2 + 1];
                if (bias) {
                    v0 += __ldg(&bias[col]);
                    v1 += __ldg(&bias[col + 1]);
                }
                if (GELU) {
                    float x3 = v0 * v0 * v0;
                    v0 = 0.5f * v0 * (1.0f + tanhf(0.7978845608028654f * (v0 + 0.044715f * x3)));
                    x3 = v1 * v1 * v1;
                    v1 = 0.5f * v1 * (1.0f + tanhf(0.7978845608028654f * (v1 + 0.044715f * x3)));
                }
                const size_t o = (size_t)z * cBS + (size_t)row * 512 + col;
                if (RES) {
                    float2 q = *(const float2*)(resp + o);
                    v0 += q.x; v1 += q.y;
                }
                if (WF32)
                    *(float2*)(C + o) = make_float2(v0, v1);
                if (WHALF)
                    *(uint32_t*)(Ch + o) = pack_hf2(v0, v1);
            }
        }
    }
}

// ------------------------- prep / elementwise kernels ----------------------
// Transpose + fp16: src [R, C] f32 -> dst [C, R] fp16
__global__ void k_thalf(const float* __restrict__ src, hf* __restrict__ dh,
                        int R, int C, size_t sBS, size_t dBS)
{
    __shared__ float tile[32][33];
    const int tx = threadIdx.x, ty = threadIdx.y;
    const int c0 = blockIdx.x * 32, r0 = blockIdx.y * 32;
    const int z = blockIdx.z;
    src += (size_t)z * sBS; dh += (size_t)z * dBS;
#pragma unroll
    for (int i = 0; i < 4; i++)
        tile[ty + i * 8][tx] = src[(size_t)(r0 + ty + i * 8) * C + c0 + tx];
    __syncthreads();
#pragma unroll
    for (int i = 0; i < 4; i++) {
        float v = tile[tx][ty + i * 8];
        dh[(size_t)(c0 + ty + i * 8) * R + r0 + tx] = __float2half_rn(v);
    }
}

// Fused 4-weight transpose+fp16 (one launch, z selects weight)
__global__ void k_thalf4(const float* __restrict__ s0, const float* __restrict__ s1,
                         const float* __restrict__ s2, const float* __restrict__ s3,
                         hf* __restrict__ dh)
{
    __shared__ float tile[32][33];
    const int tx = threadIdx.x, ty = threadIdx.y;
    const int c0 = blockIdx.x * 32, r0 = blockIdx.y * 32;
    const int z = blockIdx.z;
    const float* src = (z == 0) ? s0 : (z == 1) ? s1 : (z == 2) ? s2 : s3;
    dh += (size_t)z * 262144;
#pragma unroll
    for (int i = 0; i < 4; i++)
        tile[ty + i * 8][tx] = src[(size_t)(r0 + ty + i * 8) * 512 + c0 + tx];
    __syncthreads();
#pragma unroll
    for (int i = 0; i < 4; i++) {
        float v = tile[tx][ty + i * 8];
        dh[(size_t)(c0 + ty + i * 8) * 512 + r0 + tx] = __float2half_rn(v);
    }
}

// K_rbf -> single fp16
__global__ void k_rbf_half(const float* __restrict__ pos, const float* __restrict__ sigma,
                           hf* __restrict__ kh)
{
    size_t lin = (size_t)blockIdx.x * 256 + threadIdx.x; // < 16*512*512
    int t4 = (int)(lin & 511);
    int m = (int)((lin >> 9) & 511);
    int b = (int)(lin >> 18);
    float s = __ldg(sigma);
    float inv = 1.0f / (2.0f * s * s);
    float gm = (float)m * (1.0f / 511.0f);
    float4 p = *(const float4*)(pos + (size_t)b * Nn + t4 * 4);
    float v0 = __expf(-(gm - p.x) * (gm - p.x) * inv);
    float v1 = __expf(-(gm - p.y) * (gm - p.y) * inv);
    float v2 = __expf(-(gm - p.z) * (gm - p.z) * inv);
    float v3 = __expf(-(gm - p.w) * (gm - p.w) * inv);
    size_t o = ((size_t)b * 512 + m) * 2048 + t4 * 4;
    uint2 hh;
    hh.x = pack_hf2(v0, v1); hh.y = pack_hf2(v2, v3);
    *(uint2*)(kh + o) = hh;
}

// Head mixing -> single fp16
__global__ void k_headmix_half(const float* __restrict__ alpha,
                               const float* __restrict__ field,
                               hf* __restrict__ oh)
{
    size_t i2 = (size_t)blockIdx.x * 256 + threadIdx.x; // < 8192*512/2
    size_t idx = i2 * 2;
    int dcol = (int)(idx & 511);
    int h = dcol >> 6, dd = dcol & 63;
    size_t base = idx - dcol;
    float s0 = 0.0f, s1 = 0.0f;
#pragma unroll
    for (int k = 0; k < 8; k++) {
        float a = __ldg(&alpha[h * 8 + k]);
        const float* f = field + base + k * 64 + dd;
        s0 = fmaf(a, f[0], s0);
        s1 = fmaf(a, f[1], s1);
    }
    *(uint32_t*)(oh + idx) = pack_hf2(s0, s1);
}

template <bool HOUT>
__global__ __launch_bounds__(256)
void k_diffuse3(const float* __restrict__ in, float* __restrict__ out,
                const float* __restrict__ coef, hf* __restrict__ oh)
{
    __shared__ float s[512 * 8];
    const int t = threadIdx.x;
    const int b = blockIdx.x >> 6;
    const int d0 = (blockIdx.x & 63) * 8;
    const int dl = t & 7;
    const size_t gbase = ((size_t)b * Mm) * Dd + d0;
    const float c = DT_C * __ldg(&coef[d0 + dl]);
#pragma unroll
    for (int i = 0; i < 16; i++) {
        int idx = t + i * 256;
        s[idx] = in[gbase + (size_t)(idx >> 3) * Dd + dl];
    }
    __syncthreads();
#pragma unroll
    for (int step = 0; step < 3; step++) {
        float nv[16];
#pragma unroll
        for (int i = 0; i < 16; i++) {
            int idx = t + i * 256;
            int m = idx >> 3;
            float v = s[idx];
            float l = (m > 0) ? s[idx - 8] : v;
            float r = (m < 511) ? s[idx + 8] : v;
            nv[i] = fmaf(c, l + r - 2.0f * v, v);
        }
        __syncthreads();
#pragma unroll
        for (int i = 0; i < 16; i++) s[t + i * 256] = nv[i];
        __syncthreads();
    }
#pragma unroll
    for (int i = 0; i < 16; i++) {
        int idx = t + i * 256;
        size_t g = gbase + (size_t)(idx >> 3) * Dd + dl;
        float v = s[idx];
        out[g] = v;
        if (HOUT) oh[g] = __float2half_rn(v);
    }
}

// sample + residual + LN1 -> fp16 hi (GEMM A) + lo (LN2 residual accuracy)
__global__ __launch_bounds__(128)
void k_sample_ln(const float* __restrict__ pos, const float* __restrict__ emb,
                 const float* __restrict__ field,
                 const float* __restrict__ gam, const float* __restrict__ bet,
                 hf* __restrict__ oh, hf* __restrict__ ol)
{
    __shared__ float ssum[4], ssq[4], sstat[2];
    int row = blockIdx.x;
    int b = row >> 11;
    float p = __ldg(&pos[row]);
    float u = fminf(fmaxf(p, 0.0f), 1.0f) * (float)(Mm - 1);
    int i0 = (int)u;
    if (i0 > Mm - 2) i0 = Mm - 2;
    float w = u - (float)i0;

    const float* f0 = field + ((size_t)b * Mm + i0) * Dd;
    int t = threadIdx.x;
    int d0 = t * 4;
    float4 a = *(const float4*)(f0 + d0);
    float4 bb = *(const float4*)(f0 + Dd + d0);
    float4 e = *(const float4*)(emb + (size_t)row * Dd + d0);
    float x[4];
    x[0] = fmaf(w, bb.x - a.x, a.x) + e.x;
    x[1] = fmaf(w, bb.y - a.y, a.y) + e.y;
    x[2] = fmaf(w, bb.z - a.z, a.z) + e.z;
    x[3] = fmaf(w, bb.w - a.w, a.w) + e.w;
    float sum = x[0] + x[1] + x[2] + x[3];
    float sq = fmaf(x[0], x[0], fmaf(x[1], x[1], fmaf(x[2], x[2], x[3] * x[3])));
#pragma unroll
    for (int o = 16; o > 0; o >>= 1) {
        sum += __shfl_down_sync(0xffffffffu, sum, o);
        sq += __shfl_down_sync(0xffffffffu, sq, o);
    }
    int wd = t >> 5, ln = t & 31;
    if (ln == 0) { ssum[wd] = sum; ssq[wd] = sq; }
    __syncthreads();
    if (t == 0) {
        float S = ssum[0] + ssum[1] + ssum[2] + ssum[3];
        float Q = ssq[0] + ssq[1] + ssq[2] + ssq[3];
        float mu = S * (1.0f / Dd);
        float var = Q * (1.0f / Dd) - mu * mu;
        sstat[0] = mu;
        sstat[1] = rsqrtf(var + 1e-5f);
    }
    __syncthreads();
    float mu = sstat[0], inv = sstat[1];
    float4 g = *(const float4*)(gam + d0);
    float4 be = *(const float4*)(bet + d0);
    float y[4];
    y[0] = (x[0] - mu) * inv * g.x + be.x;
    y[1] = (x[1] - mu) * inv * g.y + be.y;
    y[2] = (x[2] - mu) * inv * g.z + be.z;
    y[3] = (x[3] - mu) * inv * g.w + be.w;
    size_t o = (size_t)row * Dd + d0;
    uint2 hh, ll;
    hh.x = pack_hf2(y[0], y[1]); hh.y = pack_hf2(y[2], y[3]);
    float h0 = __half2float(__float2half_rn(y[0]));
    float h1 = __half2float(__float2half_rn(y[1]));
    float h2 = __half2float(__float2half_rn(y[2]));
    float h3 = __half2float(__float2half_rn(y[3]));
    ll.x = pack_hf2(y[0] - h0, y[1] - h1); ll.y = pack_hf2(y[2] - h2, y[3] - h3);
    *(uint2*)(oh + o) = hh;
    *(uint2*)(ol + o) = ll;
}

// final residual + LN2 in-place on out; enh reconstructed from fp16 hi/lo
__global__ __launch_bounds__(128)
void k_ln2(const hf* __restrict__ eh, const hf* __restrict__ el,
           const float* __restrict__ gam, const float* __restrict__ bet,
           float* __restrict__ out)
{
    __shared__ float ssum[4], ssq[4], sstat[2];
    int row = blockIdx.x;
    int t = threadIdx.x;
    int d0 = t * 4;
    size_t o = (size_t)row * Dd + d0;
    float4 a = *(const float4*)(out + o);
    uint2 hv = *(const uint2*)(eh + o);
    uint2 lv = *(const uint2*)(el + o);
    __half2 h01 = *reinterpret_cast<__half2*>(&hv.x);
    __half2 h23 = *reinterpret_cast<__half2*>(&hv.y);
    __half2 l01 = *reinterpret_cast<__half2*>(&lv.x);
    __half2 l23 = *reinterpret_cast<__half2*>(&lv.y);
    float e0 = __half2float(h01.x) + __half2float(l01.x);
    float e1 = __half2float(h01.y) + __half2float(l01.y);
    float e2 = __half2float(h23.x) + __half2float(l23.x);
    float e3 = __half2float(h23.y) + __half2float(l23.y);
    float x[4] = {a.x + e0, a.y + e1, a.z + e2, a.w + e3};
    float sum = x[0] + x[1] + x[2] + x[3];
    float sq = fmaf(x[0], x[0], fmaf(x[1], x[1], fmaf(x[2], x[2], x[3] * x[3])));
#pragma unroll
    for (int s = 16; s > 0; s >>= 1) {
        sum += __shfl_down_sync(0xffffffffu, sum, s);
        sq += __shfl_down_sync(0xffffffffu, sq, s);
    }
    int wd = t >> 5, ln = t & 31;
    if (ln == 0) { ssum[wd] = sum; ssq[wd] = sq; }
    __syncthreads();
    if (t == 0) {
        float S = ssum[0] + ssum[1] + ssum[2] + ssum[3];
        float Q = ssq[0] + ssq[1] + ssq[2] + ssq[3];
        float mu = S * (1.0f / Dd);
        float var = Q * (1.0f / Dd) - mu * mu;
        sstat[0] = mu;
        sstat[1] = rsqrtf(var + 1e-5f);
    }
    __syncthreads();
    float mu = sstat[0], inv = sstat[1];
    float4 g = *(const float4*)(gam + d0);
    float4 be = *(const float4*)(bet + d0);
    *(float4*)(out + o) = make_float4(
        (x[0] - mu) * inv * g.x + be.x, (x[1] - mu) * inv * g.y + be.y,
        (x[2] - mu) * inv * g.z + be.z, (x[3] - mu) * inv * g.w + be.w);
}

// ---------------------------------------------------------------------------
extern "C" void kernel_launch(void* const* d_in, const int* in_sizes, int n_in,
                              void* d_out, int out_size)
{
    const float* emb   = (const float*)d_in[0];
    const float* pos   = (const float*)d_in[1];
    const float* sigma = (const float*)d_in[2];
    const float* alpha = (const float*)d_in[3];
    const float* w_int = (const float*)d_in[4];
    const float* b_int = (const float*)d_in[5];
    const float* dcoef = (const float*)d_in[6];
    const float* W1    = (const float*)d_in[7];
    const float* b1    = (const float*)d_in[8];
    const float* W2    = (const float*)d_in[9];
    const float* b2    = (const float*)d_in[10];
    const float* ecoef = (const float*)d_in[11];
    const float* ln1g  = (const float*)d_in[12];
    const float* ln1b  = (const float*)d_in[13];
    const float* Wout  = (const float*)d_in[14];
    const float* bout  = (const float*)d_in[15];
    const float* ln2g  = (const float*)d_in[16];
    const float* ln2b  = (const float*)d_in[17];
    float* out = (float*)d_out;

    hf *h1, *l1, *h2, *ebh, *wh;
    float *field, *tmp2;
    cudaGetSymbolAddress((void**)&h1, g_h1);
    cudaGetSymbolAddress((void**)&l1, g_l1);
    cudaGetSymbolAddress((void**)&h2, g_h2);
    cudaGetSymbolAddress((void**)&ebh, g_ebh);
    cudaGetSymbolAddress((void**)&wh, g_wh);
    cudaGetSymbolAddress((void**)&field, g_field);
    cudaGetSymbolAddress((void**)&tmp2, g_tmp2);

    cudaFuncSetAttribute(k_gemm_mma<false, false, true, false>,
                         cudaFuncAttributeMaxDynamicSharedMemorySize, SMEM_SZ);
    cudaFuncSetAttribute(k_gemm_mma<false, true, true, false>,
                         cudaFuncAttributeMaxDynamicSharedMemorySize, SMEM_SZ);
    cudaFuncSetAttribute(k_gemm_mma<true, false, false, true>,
                         cudaFuncAttributeMaxDynamicSharedMemorySize, SMEM_SZ);

    dim3 tT(32, 8);

    // weights^T fp16 (single fused launch)
    k_thalf4<<<dim3(16, 16, 4), tT>>>(w_int, W1, W2, Wout, wh);

    // embT fp16  [b, d, t]
    k_thalf<<<dim3(16, 64, 16), tT>>>(emb, ebh, Nn, Dd,
                                      (size_t)Nn * Dd, (size_t)Dd * Nn);

    // K-RBF fp16 into h1 (flat 16x512x2048)
    k_rbf_half<<<16384, 256>>>(pos, sigma, h1);

    // 1) field = K @ emb^T'   (batched, Kdim=2048)
    k_gemm_mma<false, false, true, false><<<dim3(4, 8, 16), 256, SMEM_SZ>>>(
        h1, 2048, (size_t)512 * 2048,
        ebh, 2048, (size_t)512 * 2048,
        nullptr, nullptr, field, nullptr, (size_t)512 * 512, 2048);

    // 2) head mixing -> h1 (fp16)
    k_headmix_half<<<8192, 256>>>(alpha, field, h1);

    // 3) tmp2 = field + mix @ w_int + b_int
    k_gemm_mma<false, true, true, false><<<dim3(64, 8, 1), 256, SMEM_SZ>>>(
        h1, 512, 0, wh + 0 * 262144, 512, 0,
        b_int, field, tmp2, nullptr, 0, 512);

    // 4) diffusion x3 -> field (+ fp16)
    k_diffuse3<true><<<Bn * 64, 256>>>(tmp2, field, dcoef, h1);

    // 5) gelu(field @ W1 + b1) -> h2 (fp16 only)
    k_gemm_mma<true, false, false, true><<<dim3(64, 8, 1), 256, SMEM_SZ>>>(
        h1, 512, 0, wh + 1 * 262144, 512, 0,
        b1, nullptr, nullptr, h2, 0, 512);

    // 6) tmp2 = field + gelu @ W2 + b2
    k_gemm_mma<false, true, true, false><<<dim3(64, 8, 1), 256, SMEM_SZ>>>(
        h2, 512, 0, wh + 2 * 262144, 512, 0,
        b2, field, tmp2, nullptr, 0, 512);

    // 7) diffusion x3 -> field
    k_diffuse3<false><<<Bn * 64, 256>>>(tmp2, field, ecoef, nullptr);

    // 8) enh = LN1(sample(field) + emb) -> h1 (hi) + l1 (lo)
    k_sample_ln<<<Bn * Nn, 128>>>(pos, emb, field, ln1g, ln1b, h1, l1);

    // 9) out = enh @ Wout + bout
    k_gemm_mma<false, false, true, false><<<dim3(256, 8, 1), 256, SMEM_SZ>>>(
        h1, 512, 0, wh + 3 * 262144, 512, 0,
        bout, nullptr, out, nullptr, 0, 512);

    // 10) out = LN2(out + enh)
    k_ln2<<<Bn * Nn, 128>>>(h1, l1, ln2g, ln2b, out);
}

// round 9
// speedup vs baseline: 4.9178x; 1.1078x over previous
#include <cuda_runtime.h>
#include <cuda_fp16.h>
#include <math.h>
#include <stdint.h>

#define Bn 16
#define Nn 2048
#define Dd 512
#define Mm 512
#define DT_C 0.01f

typedef __half hf;

// ------------------------- device scratch (no runtime alloc) ---------------
__device__ hf g_h1[(size_t)32768 * 512];   // 32MB  (K-RBF / field / enh hi)
__device__ hf g_l1[(size_t)32768 * 512];   // 32MB  (enh lo for LN2 residual)
__device__ hf g_h2[(size_t)8192 * 512];    // 8MB   (gelu)
__device__ hf g_ebh[(size_t)Bn * Dd * Nn]; // 32MB  embT  [b, d, t]
__device__ hf g_wh[4][512 * 512];          // 2MB   weight^T [n, k]
__device__ float g_field[(size_t)Bn * Mm * Dd]; // 16MB
__device__ float g_tmp2[(size_t)Bn * Mm * Dd];  // 16MB

// ------------------------- helpers -----------------------------------------
__device__ __forceinline__ uint32_t smem_u32(const void* p) {
    uint32_t a;
    asm("{ .reg .u64 t; cvta.to.shared.u64 t, %1; cvt.u32.u64 %0, t; }" : "=r"(a) : "l"(p));
    return a;
}
__device__ __forceinline__ uint32_t pack_hf2(float a, float b) {
    __half2 t = __floats2half2_rn(a, b);
    return *reinterpret_cast<uint32_t*>(&t);
}
__device__ __forceinline__ void cp16(uint32_t dst, const void* src) {
    asm volatile("cp.async.cg.shared.global [%0], [%1], 16;" :: "r"(dst), "l"(src));
}
__device__ __forceinline__ void cp_commit() {
    asm volatile("cp.async.commit_group;");
}
__device__ __forceinline__ void cp_wait1() {
    asm volatile("cp.async.wait_group 1;");
}
__device__ __forceinline__ void ldm_x4(uint32_t* r, uint32_t a) {
    asm volatile("ldmatrix.sync.aligned.m8n8.x4.shared.b16 {%0,%1,%2,%3}, [%4];"
                 : "=r"(r[0]), "=r"(r[1]), "=r"(r[2]), "=r"(r[3]) : "r"(a));
}
__device__ __forceinline__ void ldm_x2(uint32_t* r, uint32_t a) {
    asm volatile("ldmatrix.sync.aligned.m8n8.x2.shared.b16 {%0,%1}, [%2];"
                 : "=r"(r[0]), "=r"(r[1]) : "r"(a));
}
__device__ __forceinline__ void mma_f16(float* c, const uint32_t* a, const uint32_t* b) {
    asm volatile(
        "mma.sync.aligned.m16n8k16.row.col.f32.f16.f16.f32 "
        "{%0,%1,%2,%3}, {%4,%5,%6,%7}, {%8,%9}, {%0,%1,%2,%3};"
        : "+f"(c[0]), "+f"(c[1]), "+f"(c[2]), "+f"(c[3])
        : "r"(a[0]), "r"(a[1]), "r"(a[2]), "r"(a[3]), "r"(b[0]), "r"(b[1]));
}

// ------------------------- HMMA GEMM (fp16, single-pass) --------------------
// D[128,128] CTA tile; 8 warps 2(M)x4(N), warp tile 64x32.
// A, B single fp16 K-major. SMEM/stage: A 16K | B 16K = 32KB; 2 stages = 64KB
// -> 2 CTAs/SM.
#define STAGE_B 32768u
#define SMEM_SZ (2 * 32768)

template <bool GELU, bool RES, bool WF32, bool WHALF>
__global__ __launch_bounds__(256, 2)
void k_gemm_mma(const hf* __restrict__ A, size_t aRS, size_t aBS,
                const hf* __restrict__ B, size_t bRS, size_t bBS,
                const float* __restrict__ bias, const float* __restrict__ resp,
                float* __restrict__ C, hf* __restrict__ Ch,
                size_t cBS, int Kdim)
{
    extern __shared__ char smem[];
    const uint32_t sb = smem_u32(smem);
    const int t = threadIdx.x;
    const int wid = t >> 5;
    const int lane = t & 31;
    const int warp_m = wid & 1;   // 2 warps over M (64 rows each)
    const int warp_n = wid >> 1;  // 4 warps over N (32 cols each)

    const int m0 = blockIdx.x * 128;
    const int n0 = blockIdx.y * 128;
    const int z = blockIdx.z;

    const hf* pA = A + (size_t)z * aBS;
    const hf* pB = B + (size_t)z * bBS;

    const int NC = Kdim >> 6;

    auto load_chunk = [&](int c) {
        const uint32_t buf = sb + (uint32_t)(c & 1) * STAGE_B;
        const int k0 = c << 6;
        // A and B: 128 rows x 8 16B-segs each; 4 iters per operand
#pragma unroll
        for (int i = 0; i < 4; i++) {
            int id = t + i * 256;
            int row = id >> 3;
            int seg = id & 7;
            uint32_t soff = (uint32_t)row * 128 + (uint32_t)((seg * 16) ^ ((row & 7) << 4));
            cp16(buf + soff,         pA + (size_t)(m0 + row) * aRS + k0 + seg * 8);
            cp16(buf + 16384 + soff, pB + (size_t)(n0 + row) * bRS + k0 + seg * 8);
        }
    };

    load_chunk(0); cp_commit();
    if (NC > 1) { load_chunk(1); cp_commit(); }

    // fragment address precomputation
    const int rowA = warp_m * 64 + (lane & 15);
    const uint32_t maskA = (uint32_t)(rowA & 7) << 4;
    const uint32_t kbA = (uint32_t)(lane >> 4) * 16;
    const int rowB = warp_n * 32 + (lane & 7);
    const uint32_t maskB = (uint32_t)(rowB & 7) << 4;
    const uint32_t kbB = (uint32_t)((lane >> 3) & 1) * 16;

    float acc[4][4][4] = {};

    for (int c = 0; c < NC; c++) {
        cp_wait1();
        __syncthreads();
        const uint32_t buf = sb + (uint32_t)(c & 1) * STAGE_B;
        const uint32_t aBase = buf + (uint32_t)rowA * 128;
        const uint32_t bBase = buf + 16384 + (uint32_t)rowB * 128;

#pragma unroll
        for (int k16 = 0; k16 < 4; k16++) {
            const uint32_t koffA = ((uint32_t)k16 * 32 + kbA) ^ maskA;
            const uint32_t koffB = ((uint32_t)k16 * 32 + kbB) ^ maskB;
            uint32_t ah[4][4], bh[4][2];
#pragma unroll
            for (int mi = 0; mi < 4; mi++)
                ldm_x4(ah[mi], aBase + mi * 2048 + koffA);
#pragma unroll
            for (int ni = 0; ni < 4; ni++)
                ldm_x2(bh[ni], bBase + ni * 1024 + koffB);
#pragma unroll
            for (int mi = 0; mi < 4; mi++)
#pragma unroll
                for (int ni = 0; ni < 4; ni++)
                    mma_f16(acc[mi][ni], ah[mi], bh[ni]);
        }
        __syncthreads();
        if (c + 2 < NC) load_chunk(c + 2);
        cp_commit();
    }

    // ------------------------- epilogue -------------------------
    const int rbase = m0 + warp_m * 64 + (lane >> 2);
    const int cbase = n0 + warp_n * 32 + (lane & 3) * 2;
#pragma unroll
    for (int mi = 0; mi < 4; mi++) {
#pragma unroll
        for (int half = 0; half < 2; half++) {
            const int row = rbase + mi * 16 + half * 8;
#pragma unroll
            for (int ni = 0; ni < 4; ni++) {
                const int col = cbase + ni * 8;
                float v0 = acc[mi][ni][half * 2 + 0];
                float v1 = acc[mi][ni][half * 2 + 1];
                if (bias) {
                    v0 += __ldg(&bias[col]);
                    v1 += __ldg(&bias[col + 1]);
                }
                if (GELU) {
                    float x3 = v0 * v0 * v0;
                    v0 = 0.5f * v0 * (1.0f + tanhf(0.7978845608028654f * (v0 + 0.044715f * x3)));
                    x3 = v1 * v1 * v1;
                    v1 = 0.5f * v1 * (1.0f + tanhf(0.7978845608028654f * (v1 + 0.044715f * x3)));
                }
                const size_t o = (size_t)z * cBS + (size_t)row * 512 + col;
                if (RES) {
                    float2 q = *(const float2*)(resp + o);
                    v0 += q.x; v1 += q.y;
                }
                if (WF32)
                    *(float2*)(C + o) = make_float2(v0, v1);
                if (WHALF)
                    *(uint32_t*)(Ch + o) = pack_hf2(v0, v1);
            }
        }
    }
}

// ------------------------- prep / elementwise kernels ----------------------
// Transpose + fp16: src [R, C] f32 -> dst [C, R] fp16
__global__ void k_thalf(const float* __restrict__ src, hf* __restrict__ dh,
                        int R, int C, size_t sBS, size_t dBS)
{
    __shared__ float tile[32][33];
    const int tx = threadIdx.x, ty = threadIdx.y;
    const int c0 = blockIdx.x * 32, r0 = blockIdx.y * 32;
    const int z = blockIdx.z;
    src += (size_t)z * sBS; dh += (size_t)z * dBS;
#pragma unroll
    for (int i = 0; i < 4; i++)
        tile[ty + i * 8][tx] = src[(size_t)(r0 + ty + i * 8) * C + c0 + tx];
    __syncthreads();
#pragma unroll
    for (int i = 0; i < 4; i++) {
        float v = tile[tx][ty + i * 8];
        dh[(size_t)(c0 + ty + i * 8) * R + r0 + tx] = __float2half_rn(v);
    }
}

// Fused 4-weight transpose+fp16 (one launch, z selects weight)
__global__ void k_thalf4(const float* __restrict__ s0, const float* __restrict__ s1,
                         const float* __restrict__ s2, const float* __restrict__ s3,
                         hf* __restrict__ dh)
{
    __shared__ float tile[32][33];
    const int tx = threadIdx.x, ty = threadIdx.y;
    const int c0 = blockIdx.x * 32, r0 = blockIdx.y * 32;
    const int z = blockIdx.z;
    const float* src = (z == 0) ? s0 : (z == 1) ? s1 : (z == 2) ? s2 : s3;
    dh += (size_t)z * 262144;
#pragma unroll
    for (int i = 0; i < 4; i++)
        tile[ty + i * 8][tx] = src[(size_t)(r0 + ty + i * 8) * 512 + c0 + tx];
    __syncthreads();
#pragma unroll
    for (int i = 0; i < 4; i++) {
        float v = tile[tx][ty + i * 8];
        dh[(size_t)(c0 + ty + i * 8) * 512 + r0 + tx] = __float2half_rn(v);
    }
}

// K_rbf -> single fp16
__global__ void k_rbf_half(const float* __restrict__ pos, const float* __restrict__ sigma,
                           hf* __restrict__ kh)
{
    size_t lin = (size_t)blockIdx.x * 256 + threadIdx.x; // < 16*512*512
    int t4 = (int)(lin & 511);
    int m = (int)((lin >> 9) & 511);
    int b = (int)(lin >> 18);
    float s = __ldg(sigma);
    float inv = 1.0f / (2.0f * s * s);
    float gm = (float)m * (1.0f / 511.0f);
    float4 p = *(const float4*)(pos + (size_t)b * Nn + t4 * 4);
    float v0 = __expf(-(gm - p.x) * (gm - p.x) * inv);
    float v1 = __expf(-(gm - p.y) * (gm - p.y) * inv);
    float v2 = __expf(-(gm - p.z) * (gm - p.z) * inv);
    float v3 = __expf(-(gm - p.w) * (gm - p.w) * inv);
    size_t o = ((size_t)b * 512 + m) * 2048 + t4 * 4;
    uint2 hh;
    hh.x = pack_hf2(v0, v1); hh.y = pack_hf2(v2, v3);
    *(uint2*)(kh + o) = hh;
}

// Head mixing -> single fp16
__global__ void k_headmix_half(const float* __restrict__ alpha,
                               const float* __restrict__ field,
                               hf* __restrict__ oh)
{
    size_t i2 = (size_t)blockIdx.x * 256 + threadIdx.x; // < 8192*512/2
    size_t idx = i2 * 2;
    int dcol = (int)(idx & 511);
    int h = dcol >> 6, dd = dcol & 63;
    size_t base = idx - dcol;
    float s0 = 0.0f, s1 = 0.0f;
#pragma unroll
    for (int k = 0; k < 8; k++) {
        float a = __ldg(&alpha[h * 8 + k]);
        const float* f = field + base + k * 64 + dd;
        s0 = fmaf(a, f[0], s0);
        s1 = fmaf(a, f[1], s1);
    }
    *(uint32_t*)(oh + idx) = pack_hf2(s0, s1);
}

template <bool HOUT>
__global__ __launch_bounds__(256)
void k_diffuse3(const float* __restrict__ in, float* __restrict__ out,
                const float* __restrict__ coef, hf* __restrict__ oh)
{
    __shared__ float s[512 * 8];
    const int t = threadIdx.x;
    const int b = blockIdx.x >> 6;
    const int d0 = (blockIdx.x & 63) * 8;
    const int dl = t & 7;
    const size_t gbase = ((size_t)b * Mm) * Dd + d0;
    const float c = DT_C * __ldg(&coef[d0 + dl]);
#pragma unroll
    for (int i = 0; i < 16; i++) {
        int idx = t + i * 256;
        s[idx] = in[gbase + (size_t)(idx >> 3) * Dd + dl];
    }
    __syncthreads();
#pragma unroll
    for (int step = 0; step < 3; step++) {
        float nv[16];
#pragma unroll
        for (int i = 0; i < 16; i++) {
            int idx = t + i * 256;
            int m = idx >> 3;
            float v = s[idx];
            float l = (m > 0) ? s[idx - 8] : v;
            float r = (m < 511) ? s[idx + 8] : v;
            nv[i] = fmaf(c, l + r - 2.0f * v, v);
        }
        __syncthreads();
#pragma unroll
        for (int i = 0; i < 16; i++) s[t + i * 256] = nv[i];
        __syncthreads();
    }
#pragma unroll
    for (int i = 0; i < 16; i++) {
        int idx = t + i * 256;
        size_t g = gbase + (size_t)(idx >> 3) * Dd + dl;
        float v = s[idx];
        out[g] = v;
        if (HOUT) oh[g] = __float2half_rn(v);
    }
}

// sample + residual + LN1 -> fp16 hi (GEMM A) + lo (LN2 residual accuracy)
__global__ __launch_bounds__(128)
void k_sample_ln(const float* __restrict__ pos, const float* __restrict__ emb,
                 const float* __restrict__ field,
                 const float* __restrict__ gam, const float* __restrict__ bet,
                 hf* __restrict__ oh, hf* __restrict__ ol)
{
    __shared__ float ssum[4], ssq[4], sstat[2];
    int row = blockIdx.x;
    int b = row >> 11;
    float p = __ldg(&pos[row]);
    float u = fminf(fmaxf(p, 0.0f), 1.0f) * (float)(Mm - 1);
    int i0 = (int)u;
    if (i0 > Mm - 2) i0 = Mm - 2;
    float w = u - (float)i0;

    const float* f0 = field + ((size_t)b * Mm + i0) * Dd;
    int t = threadIdx.x;
    int d0 = t * 4;
    float4 a = *(const float4*)(f0 + d0);
    float4 bb = *(const float4*)(f0 + Dd + d0);
    float4 e = *(const float4*)(emb + (size_t)row * Dd + d0);
    float x[4];
    x[0] = fmaf(w, bb.x - a.x, a.x) + e.x;
    x[1] = fmaf(w, bb.y - a.y, a.y) + e.y;
    x[2] = fmaf(w, bb.z - a.z, a.z) + e.z;
    x[3] = fmaf(w, bb.w - a.w, a.w) + e.w;
    float sum = x[0] + x[1] + x[2] + x[3];
    float sq = fmaf(x[0], x[0], fmaf(x[1], x[1], fmaf(x[2], x[2], x[3] * x[3])));
#pragma unroll
    for (int o = 16; o > 0; o >>= 1) {
        sum += __shfl_down_sync(0xffffffffu, sum, o);
        sq += __shfl_down_sync(0xffffffffu, sq, o);
    }
    int wd = t >> 5, ln = t & 31;
    if (ln == 0) { ssum[wd] = sum; ssq[wd] = sq; }
    __syncthreads();
    if (t == 0) {
        float S = ssum[0] + ssum[1] + ssum[2] + ssum[3];
        float Q = ssq[0] + ssq[1] + ssq[2] + ssq[3];
        float mu = S * (1.0f / Dd);
        float var = Q * (1.0f / Dd) - mu * mu;
        sstat[0] = mu;
        sstat[1] = rsqrtf(var + 1e-5f);
    }
    __syncthreads();
    float mu = sstat[0], inv = sstat[1];
    float4 g = *(const float4*)(gam + d0);
    float4 be = *(const float4*)(bet + d0);
    float y[4];
    y[0] = (x[0] - mu) * inv * g.x + be.x;
    y[1] = (x[1] - mu) * inv * g.y + be.y;
    y[2] = (x[2] - mu) * inv * g.z + be.z;
    y[3] = (x[3] - mu) * inv * g.w + be.w;
    size_t o = (size_t)row * Dd + d0;
    uint2 hh, ll;
    hh.x = pack_hf2(y[0], y[1]); hh.y = pack_hf2(y[2], y[3]);
    float h0 = __half2float(__float2half_rn(y[0]));
    float h1 = __half2float(__float2half_rn(y[1]));
    float h2 = __half2float(__float2half_rn(y[2]));
    float h3 = __half2float(__float2half_rn(y[3]));
    ll.x = pack_hf2(y[0] - h0, y[1] - h1); ll.y = pack_hf2(y[2] - h2, y[3] - h3);
    *(uint2*)(oh + o) = hh;
    *(uint2*)(ol + o) = ll;
}

// final residual + LN2 in-place on out; enh reconstructed from fp16 hi/lo
__global__ __launch_bounds__(128)
void k_ln2(const hf* __restrict__ eh, const hf* __restrict__ el,
           const float* __restrict__ gam, const float* __restrict__ bet,
           float* __restrict__ out)
{
    __shared__ float ssum[4], ssq[4], sstat[2];
    int row = blockIdx.x;
    int t = threadIdx.x;
    int d0 = t * 4;
    size_t o = (size_t)row * Dd + d0;
    float4 a = *(const float4*)(out + o);
    uint2 hv = *(const uint2*)(eh + o);
    uint2 lv = *(const uint2*)(el + o);
    __half2 h01 = *reinterpret_cast<__half2*>(&hv.x);
    __half2 h23 = *reinterpret_cast<__half2*>(&hv.y);
    __half2 l01 = *reinterpret_cast<__half2*>(&lv.x);
    __half2 l23 = *reinterpret_cast<__half2*>(&lv.y);
    float e0 = __half2float(h01.x) + __half2float(l01.x);
    float e1 = __half2float(h01.y) + __half2float(l01.y);
    float e2 = __half2float(h23.x) + __half2float(l23.x);
    float e3 = __half2float(h23.y) + __half2float(l23.y);
    float x[4] = {a.x + e0, a.y + e1, a.z + e2, a.w + e3};
    float sum = x[0] + x[1] + x[2] + x[3];
    float sq = fmaf(x[0], x[0], fmaf(x[1], x[1], fmaf(x[2], x[2], x[3] * x[3])));
#pragma unroll
    for (int s = 16; s > 0; s >>= 1) {
        sum += __shfl_down_sync(0xffffffffu, sum, s);
        sq += __shfl_down_sync(0xffffffffu, sq, s);
    }
    int wd = t >> 5, ln = t & 31;
    if (ln == 0) { ssum[wd] = sum; ssq[wd] = sq; }
    __syncthreads();
    if (t == 0) {
        float S = ssum[0] + ssum[1] + ssum[2] + ssum[3];
        float Q = ssq[0] + ssq[1] + ssq[2] + ssq[3];
        float mu = S * (1.0f / Dd);
        float var = Q * (1.0f / Dd) - mu * mu;
        sstat[0] = mu;
        sstat[1] = rsqrtf(var + 1e-5f);
    }
    __syncthreads();
    float mu = sstat[0], inv = sstat[1];
    float4 g = *(const float4*)(gam + d0);
    float4 be = *(const float4*)(bet + d0);
    *(float4*)(out + o) = make_float4(
        (x[0] - mu) * inv * g.x + be.x, (x[1] - mu) * inv * g.y + be.y,
        (x[2] - mu) * inv * g.z + be.z, (x[3] - mu) * inv * g.w + be.w);
}

// ---------------------------------------------------------------------------
extern "C" void kernel_launch(void* const* d_in, const int* in_sizes, int n_in,
                              void* d_out, int out_size)
{
    const float* emb   = (const float*)d_in[0];
    const float* pos   = (const float*)d_in[1];
    const float* sigma = (const float*)d_in[2];
    const float* alpha = (const float*)d_in[3];
    const float* w_int = (const float*)d_in[4];
    const float* b_int = (const float*)d_in[5];
    const float* dcoef = (const float*)d_in[6];
    const float* W1    = (const float*)d_in[7];
    const float* b1    = (const float*)d_in[8];
    const float* W2    = (const float*)d_in[9];
    const float* b2    = (const float*)d_in[10];
    const float* ecoef = (const float*)d_in[11];
    const float* ln1g  = (const float*)d_in[12];
    const float* ln1b  = (const float*)d_in[13];
    const float* Wout  = (const float*)d_in[14];
    const float* bout  = (const float*)d_in[15];
    const float* ln2g  = (const float*)d_in[16];
    const float* ln2b  = (const float*)d_in[17];
    float* out = (float*)d_out;

    hf *h1, *l1, *h2, *ebh, *wh;
    float *field, *tmp2;
    cudaGetSymbolAddress((void**)&h1, g_h1);
    cudaGetSymbolAddress((void**)&l1, g_l1);
    cudaGetSymbolAddress((void**)&h2, g_h2);
    cudaGetSymbolAddress((void**)&ebh, g_ebh);
    cudaGetSymbolAddress((void**)&wh, g_wh);
    cudaGetSymbolAddress((void**)&field, g_field);
    cudaGetSymbolAddress((void**)&tmp2, g_tmp2);

    cudaFuncSetAttribute(k_gemm_mma<false, false, true, false>,
                         cudaFuncAttributeMaxDynamicSharedMemorySize, SMEM_SZ);
    cudaFuncSetAttribute(k_gemm_mma<false, true, true, false>,
                         cudaFuncAttributeMaxDynamicSharedMemorySize, SMEM_SZ);
    cudaFuncSetAttribute(k_gemm_mma<true, false, false, true>,
                         cudaFuncAttributeMaxDynamicSharedMemorySize, SMEM_SZ);

    dim3 tT(32, 8);

    // weights^T fp16 (single fused launch)
    k_thalf4<<<dim3(16, 16, 4), tT>>>(w_int, W1, W2, Wout, wh);

    // embT fp16  [b, d, t]
    k_thalf<<<dim3(16, 64, 16), tT>>>(emb, ebh, Nn, Dd,
                                      (size_t)Nn * Dd, (size_t)Dd * Nn);

    // K-RBF fp16 into h1 (flat 16x512x2048)
    k_rbf_half<<<16384, 256>>>(pos, sigma, h1);

    // 1) field = K @ emb^T'   (batched, Kdim=2048)
    k_gemm_mma<false, false, true, false><<<dim3(4, 4, 16), 256, SMEM_SZ>>>(
        h1, 2048, (size_t)512 * 2048,
        ebh, 2048, (size_t)512 * 2048,
        nullptr, nullptr, field, nullptr, (size_t)512 * 512, 2048);

    // 2) head mixing -> h1 (fp16)
    k_headmix_half<<<8192, 256>>>(alpha, field, h1);

    // 3) tmp2 = field + mix @ w_int + b_int
    k_gemm_mma<false, true, true, false><<<dim3(64, 4, 1), 256, SMEM_SZ>>>(
        h1, 512, 0, wh + 0 * 262144, 512, 0,
        b_int, field, tmp2, nullptr, 0, 512);

    // 4) diffusion x3 -> field (+ fp16)
    k_diffuse3<true><<<Bn * 64, 256>>>(tmp2, field, dcoef, h1);

    // 5) gelu(field @ W1 + b1) -> h2 (fp16 only)
    k_gemm_mma<true, false, false, true><<<dim3(64, 4, 1), 256, SMEM_SZ>>>(
        h1, 512, 0, wh + 1 * 262144, 512, 0,
        b1, nullptr, nullptr, h2, 0, 512);

    // 6) tmp2 = field + gelu @ W2 + b2
    k_gemm_mma<false, true, true, false><<<dim3(64, 4, 1), 256, SMEM_SZ>>>(
        h2, 512, 0, wh + 2 * 262144, 512, 0,
        b2, field, tmp2, nullptr, 0, 512);

    // 7) diffusion x3 -> field
    k_diffuse3<false><<<Bn * 64, 256>>>(tmp2, field, ecoef, nullptr);

    // 8) enh = LN1(sample(field) + emb) -> h1 (hi) + l1 (lo)
    k_sample_ln<<<Bn * Nn, 128>>>(pos, emb, field, ln1g, ln1b, h1, l1);

    // 9) out = enh @ Wout + bout
    k_gemm_mma<false, false, true, false><<<dim3(256, 4, 1), 256, SMEM_SZ>>>(
        h1, 512, 0, wh + 3 * 262144, 512, 0,
        bout, nullptr, out, nullptr, 0, 512);

    // 10) out = LN2(out + enh)
    k_ln2<<<Bn * Nn, 128>>>(h1, l1, ln2g, ln2b, out);
}